// round 6
// baseline (speedup 1.0000x reference)
#include <cuda_runtime.h>
#include <stdint.h>
#include <math.h>

#define BB    4
#define TSEQ  2048
#define DM    1024
#define DI    2048
#define DS_   16
#define DTR   64
#define FFND  3584
#define MROWS (BB*TSEQ)   // 8192
#define NC    64          // scan chunks
#define CL    32          // chunk length

// ---------------- static device scratch -----------------------------------
__device__ float g_X  [MROWS*DM];
__device__ float g_Xn [MROWS*DM];
__device__ float g_xz [MROWS*2*DI];
__device__ float g_xc [MROWS*DI];
__device__ float g_xd [MROWS*96];
__device__ float g_dt [MROWS*DI];
__device__ float g_ym [MROWS*DI];
__device__ float g_ffn[MROWS*FFND];
__device__ float g_cP [BB*NC*DI*DS_];
__device__ float g_cS [BB*NC*DI*DS_];
__device__ float g_cI [BB*NC*DI*DS_];
__device__ float g_wa [4096*1024];       // tf32-rounded weight scratch

__device__ __forceinline__ float rndtf(float f) {
    uint32_t u; asm("cvt.rna.tf32.f32 %0, %1;" : "=r"(u) : "f"(f));
    return __uint_as_float(u);
}
__device__ __forceinline__ void cpasync16(uint32_t dst, const void* src) {
    asm volatile("cp.async.ca.shared.global [%0], [%1], 16;" :: "r"(dst), "l"(src));
}
__device__ __forceinline__ void mma_tf32(float c[4], const uint32_t a[4], const uint32_t b[2]) {
    asm volatile(
        "mma.sync.aligned.m16n8k8.row.col.f32.tf32.tf32.f32 "
        "{%0,%1,%2,%3}, {%4,%5,%6,%7}, {%8,%9}, {%0,%1,%2,%3};"
        : "+f"(c[0]), "+f"(c[1]), "+f"(c[2]), "+f"(c[3])
        : "r"(a[0]), "r"(a[1]), "r"(a[2]), "r"(a[3]), "r"(b[0]), "r"(b[1]));
}

// ---------------- weight pre-round (rna to tf32) ---------------------------
__global__ void k_round(const float* __restrict__ in, float* __restrict__ out, int n4) {
    int i = blockIdx.x * 256 + threadIdx.x;
    if (i < n4) {
        float4 v = ((const float4*)in)[i];
        v.x = rndtf(v.x); v.y = rndtf(v.y); v.z = rndtf(v.z); v.w = rndtf(v.w);
        ((float4*)out)[i] = v;
    }
}

// ---------------- positional encoding --------------------------------------
__global__ void k_add_pe(const float* __restrict__ xin, float* __restrict__ X) {
    int idx = blockIdx.x * 256 + threadIdx.x;
    int d = idx & (DM - 1);
    int m = idx >> 10;
    int t = m & (TSEQ - 1);
    int p2 = d & ~1;
    float freq = expf((float)p2 * (-9.210340371976184f / (float)DM));
    float ang = (float)t * freq;
    float pe = (d & 1) ? cosf(ang) : sinf(ang);
    X[idx] = xin[idx] + pe;
}

// ---------------- layernorm -------------------------------------------------
__device__ __forceinline__ float blockReduce(float v, float* sh) {
    int lane = threadIdx.x & 31, wid = threadIdx.x >> 5;
    #pragma unroll
    for (int o = 16; o > 0; o >>= 1) v += __shfl_down_sync(0xffffffffu, v, o);
    if (lane == 0) sh[wid] = v;
    __syncthreads();
    if (threadIdx.x == 0) {
        float s = 0.f;
        #pragma unroll
        for (int i = 0; i < 8; i++) s += sh[i];
        sh[32] = s;
    }
    __syncthreads();
    float r = sh[32];
    __syncthreads();
    return r;
}

__global__ __launch_bounds__(256) void k_ln(const float* __restrict__ in,
                                            float* __restrict__ out,
                                            const float* __restrict__ g,
                                            const float* __restrict__ b, int rnd) {
    __shared__ float sh[33];
    int row = blockIdx.x;
    float4 v = ((const float4*)(in + (size_t)row * DM))[threadIdx.x];
    float mean = blockReduce(v.x + v.y + v.z + v.w, sh) * (1.0f / DM);
    float dx = v.x - mean, dy = v.y - mean, dz = v.z - mean, dw = v.w - mean;
    float var = blockReduce(dx*dx + dy*dy + dz*dz + dw*dw, sh) * (1.0f / DM);
    float rstd = rsqrtf(var + 1e-5f);
    int c = threadIdx.x * 4;
    float4 o;
    o.x = dx * rstd * g[c + 0] + b[c + 0];
    o.y = dy * rstd * g[c + 1] + b[c + 1];
    o.z = dz * rstd * g[c + 2] + b[c + 2];
    o.w = dw * rstd * g[c + 3] + b[c + 3];
    if (rnd) { o.x = rndtf(o.x); o.y = rndtf(o.y); o.z = rndtf(o.z); o.w = rndtf(o.w); }
    ((float4*)(out + (size_t)row * DM))[threadIdx.x] = o;
}

// ---------------- tf32 tensor-core GEMM -------------------------------------
// C[m,n] = sum_k A[m,k] * W[n,k]
// CTA tile 128(M) x 256(N), 256 threads (8 warps, 2x4), warp tile 64x64.
// Inputs MUST be pre-rounded to tf32 (weights via k_round, activations at source).
// epi: 0:store 1:+bias 2:gelu(rnd) 3:C+= 4:C+=+bias 5:softplus+bias 6:store(rnd)
#define GBK    16
#define GPAD   20
#define ABUFW  (128 * GPAD)            // words per A buffer
#define BBUFW  (256 * GPAD)
#define SMEM6  ((2*ABUFW + 2*BBUFW) * 4)   // 61440 bytes

__global__ __launch_bounds__(256, 1) void k_gemm_tc(
    const float* __restrict__ A, const float* __restrict__ W,
    float* __restrict__ C, const float* __restrict__ bias,
    int N, int K, int lda, int ldw, int ldc, int epi) {
    extern __shared__ float sm6[];
    float* As = sm6;                     // [2][ABUFW]
    float* Bs = sm6 + 2 * ABUFW;         // [2][BBUFW]
    const int tid = threadIdx.x;
    const int lane = tid & 31;
    const int wid = tid >> 5;
    const int wm = wid & 1;              // 2 x 64 rows
    const int wn = wid >> 1;             // 4 x 64 cols
    const int g = lane >> 2, tig = lane & 3;
    const int bM = blockIdx.y * 128, bN = blockIdx.x * 256;

    // loaders
    const int lrow = tid >> 1;
    const int lhalf = (tid & 1) << 3;    // 0 or 8
    const float* Ag = A + (size_t)(bM + lrow) * lda + lhalf;
    int wr0 = bN + lrow;       if (wr0 >= N) wr0 = N - 1;
    int wr1 = bN + 128 + lrow; if (wr1 >= N) wr1 = N - 1;
    const float* Wg0 = W + (size_t)wr0 * ldw + lhalf;
    const float* Wg1 = W + (size_t)wr1 * ldw + lhalf;

    const uint32_t sA0 = (uint32_t)__cvta_generic_to_shared(As);
    const uint32_t sB0 = (uint32_t)__cvta_generic_to_shared(Bs);
    const uint32_t dstA = (uint32_t)lrow * GPAD * 4 + (uint32_t)lhalf * 4;
    const uint32_t dstB0 = dstA;
    const uint32_t dstB1 = (uint32_t)(lrow + 128) * GPAD * 4 + (uint32_t)lhalf * 4;

    float acc[4][8][4];
    #pragma unroll
    for (int i = 0; i < 4; i++)
        #pragma unroll
        for (int j = 0; j < 8; j++)
            #pragma unroll
            for (int q = 0; q < 4; q++) acc[i][j][q] = 0.f;

    const int KT = K / GBK;
    #pragma unroll
    for (int c = 0; c < 2; c++) {
        cpasync16(sA0 + dstA + c * 16, Ag + c * 4);
        cpasync16(sB0 + dstB0 + c * 16, Wg0 + c * 4);
        cpasync16(sB0 + dstB1 + c * 16, Wg1 + c * 4);
    }
    asm volatile("cp.async.commit_group;");

    for (int kt = 0; kt < KT; kt++) {
        const int buf = kt & 1;
        if (kt + 1 < KT) {
            const int nb = buf ^ 1;
            const int k2 = (kt + 1) * GBK;
            #pragma unroll
            for (int c = 0; c < 2; c++) {
                cpasync16(sA0 + nb * ABUFW * 4 + dstA + c * 16, Ag + k2 + c * 4);
                cpasync16(sB0 + nb * BBUFW * 4 + dstB0 + c * 16, Wg0 + k2 + c * 4);
                cpasync16(sB0 + nb * BBUFW * 4 + dstB1 + c * 16, Wg1 + k2 + c * 4);
            }
            asm volatile("cp.async.commit_group;");
            asm volatile("cp.async.wait_group 1;");
        } else {
            asm volatile("cp.async.wait_group 0;");
        }
        __syncthreads();

        const uint32_t* as = (const uint32_t*)(As + buf * ABUFW);
        const uint32_t* bs = (const uint32_t*)(Bs + buf * BBUFW);
        #pragma unroll
        for (int ks = 0; ks < 2; ks++) {
            const int kk = ks * 8 + tig;
            uint32_t af[4][4], bf[8][2];
            #pragma unroll
            for (int i = 0; i < 4; i++) {
                const int r = wm * 64 + i * 16 + g;
                af[i][0] = as[r * GPAD + kk];
                af[i][1] = as[(r + 8) * GPAD + kk];
                af[i][2] = as[r * GPAD + kk + 4];
                af[i][3] = as[(r + 8) * GPAD + kk + 4];
            }
            #pragma unroll
            for (int j = 0; j < 8; j++) {
                const int cn = wn * 64 + j * 8 + g;
                bf[j][0] = bs[cn * GPAD + kk];
                bf[j][1] = bs[cn * GPAD + kk + 4];
            }
            #pragma unroll
            for (int i = 0; i < 4; i++)
                #pragma unroll
                for (int j = 0; j < 8; j++)
                    mma_tf32(acc[i][j], af[i], bf[j]);
        }
        __syncthreads();
    }

    // epilogue
    #pragma unroll
    for (int i = 0; i < 4; i++) {
        const int r0 = bM + wm * 64 + i * 16 + g;
        #pragma unroll
        for (int j = 0; j < 8; j++) {
            const int cn = bN + wn * 64 + j * 8 + tig * 2;
            #pragma unroll
            for (int q = 0; q < 4; q++) {
                const int r = r0 + (q >> 1) * 8;
                const int c = cn + (q & 1);
                if (c >= N) continue;
                float v = acc[i][j][q];
                float* cp = C + (size_t)r * ldc + c;
                if (epi == 0) { *cp = v; }
                else if (epi == 1) { *cp = v + bias[c]; }
                else if (epi == 2) {
                    float u = v + bias[c];
                    *cp = rndtf(0.5f * u * (1.0f + erff(u * 0.70710678118654752f)));
                } else if (epi == 3) { *cp = *cp + v; }
                else if (epi == 4) { *cp = *cp + v + bias[c]; }
                else if (epi == 5) {
                    float u = v + bias[c];
                    *cp = (u > 20.f) ? u : log1pf(expf(u));
                } else { *cp = rndtf(v); }
            }
        }
    }
}

// ---------------- causal depthwise conv (k=4) + silu -----------------------
__global__ void k_conv(const float* __restrict__ xz, const float* __restrict__ cw,
                       const float* __restrict__ cb, float* __restrict__ xc) {
    int idx = blockIdx.x * 256 + threadIdx.x;
    int d = idx & (DI - 1);
    int m = idx >> 11;
    int t = m & (TSEQ - 1);
    float acc = cb[d];
    #pragma unroll
    for (int k = 0; k < 4; k++) {
        int tt = t + k - 3;
        if (tt >= 0) acc += xz[(size_t)(m + k - 3) * (2 * DI) + d] * cw[d * 4 + k];
    }
    float sg = 1.0f / (1.0f + expf(-acc));
    xc[idx] = rndtf(acc * sg);
}

// ---------------- scan pass A -----------------------------------------------
__global__ __launch_bounds__(256) void k_scanA(
    const float* __restrict__ dt, const float* __restrict__ xc,
    const float* __restrict__ xd, const float* __restrict__ Alog,
    float* __restrict__ gP, float* __restrict__ gS) {
    __shared__ float shB[CL][DS_];
    int b = blockIdx.z, c = blockIdx.y;
    int d = blockIdx.x * 256 + threadIdx.x;
    int mbase = b * TSEQ + c * CL;
    for (int idx = threadIdx.x; idx < CL * DS_; idx += 256) {
        int t = idx >> 4, col = idx & 15;
        shB[t][col] = xd[(size_t)(mbase + t) * 96 + 64 + col];
    }
    __syncthreads();
    float r[DS_];
    bool fast = true;
    #pragma unroll
    for (int n = 0; n < DS_; n++) {
        r[n] = expf(Alog[(size_t)d * DS_ + n]);
        fast = fast && (fabsf(r[n] - (float)(n + 1)) < 1e-3f * (float)(n + 1));
    }
    float P[DS_], S[DS_];
    #pragma unroll
    for (int n = 0; n < DS_; n++) { P[n] = 1.f; S[n] = 0.f; }
    for (int t = 0; t < CL; t++) {
        int m = mbase + t;
        float dv = dt[(size_t)m * DI + d];
        float xv = xc[(size_t)m * DI + d];
        float u = xv * dv;
        float dA[DS_];
        if (fast) {
            float e = expf(-dv);
            float p = 1.f;
            #pragma unroll
            for (int n = 0; n < DS_; n++) { p *= e; dA[n] = p; }
        } else {
            #pragma unroll
            for (int n = 0; n < DS_; n++) dA[n] = expf(-dv * r[n]);
        }
        #pragma unroll
        for (int n = 0; n < DS_; n++) {
            S[n] = S[n] * dA[n] + u * shB[t][n];
            P[n] *= dA[n];
        }
    }
    size_t base = (((size_t)b * NC + c) * DI + d) * DS_;
    #pragma unroll
    for (int n = 0; n < DS_; n += 4) {
        *(float4*)(gP + base + n) = make_float4(P[n], P[n+1], P[n+2], P[n+3]);
        *(float4*)(gS + base + n) = make_float4(S[n], S[n+1], S[n+2], S[n+3]);
    }
}

// ---------------- scan pass B -----------------------------------------------
__global__ void k_scanB(const float* __restrict__ gP, const float* __restrict__ gS,
                        float* __restrict__ gI) {
    int idx = blockIdx.x * 256 + threadIdx.x;
    int b = idx >> 11, d = idx & (DI - 1);
    float s[DS_];
    #pragma unroll
    for (int n = 0; n < DS_; n++) s[n] = 0.f;
    for (int c = 0; c < NC; c++) {
        size_t base = (((size_t)b * NC + c) * DI + d) * DS_;
        #pragma unroll
        for (int n = 0; n < DS_; n += 4)
            *(float4*)(gI + base + n) = make_float4(s[n], s[n+1], s[n+2], s[n+3]);
        #pragma unroll
        for (int n = 0; n < DS_; n += 4) {
            float4 P = *(const float4*)(gP + base + n);
            float4 S = *(const float4*)(gS + base + n);
            s[n+0] = s[n+0] * P.x + S.x;
            s[n+1] = s[n+1] * P.y + S.y;
            s[n+2] = s[n+2] * P.z + S.z;
            s[n+3] = s[n+3] * P.w + S.w;
        }
    }
}

// ---------------- scan pass C -----------------------------------------------
__global__ __launch_bounds__(256) void k_scanC(
    const float* __restrict__ dt, const float* __restrict__ xc,
    const float* __restrict__ xd, const float* __restrict__ xz,
    const float* __restrict__ Alog, const float* __restrict__ Dsk,
    const float* __restrict__ gI, float* __restrict__ ym) {
    __shared__ float shB[CL][DS_];
    __shared__ float shC[CL][DS_];
    int b = blockIdx.z, c = blockIdx.y;
    int d = blockIdx.x * 256 + threadIdx.x;
    int mbase = b * TSEQ + c * CL;
    for (int idx = threadIdx.x; idx < CL * 32; idx += 256) {
        int t = idx >> 5, col = idx & 31;
        float v = xd[(size_t)(mbase + t) * 96 + 64 + col];
        if (col < 16) shB[t][col] = v;
        else shC[t][col - 16] = v;
    }
    __syncthreads();
    float r[DS_];
    bool fast = true;
    #pragma unroll
    for (int n = 0; n < DS_; n++) {
        r[n] = expf(Alog[(size_t)d * DS_ + n]);
        fast = fast && (fabsf(r[n] - (float)(n + 1)) < 1e-3f * (float)(n + 1));
    }
    float dskip = Dsk[d];
    float s[DS_];
    size_t base = (((size_t)b * NC + c) * DI + d) * DS_;
    #pragma unroll
    for (int n = 0; n < DS_; n += 4) {
        float4 v = *(const float4*)(gI + base + n);
        s[n+0] = v.x; s[n+1] = v.y; s[n+2] = v.z; s[n+3] = v.w;
    }
    for (int t = 0; t < CL; t++) {
        int m = mbase + t;
        float dv = dt[(size_t)m * DI + d];
        float xv = xc[(size_t)m * DI + d];
        float u = xv * dv;
        float dA[DS_];
        if (fast) {
            float e = expf(-dv);
            float p = 1.f;
            #pragma unroll
            for (int n = 0; n < DS_; n++) { p *= e; dA[n] = p; }
        } else {
            #pragma unroll
            for (int n = 0; n < DS_; n++) dA[n] = expf(-dv * r[n]);
        }
        float y = 0.f;
        #pragma unroll
        for (int n = 0; n < DS_; n++) {
            s[n] = s[n] * dA[n] + u * shB[t][n];
            y += s[n] * shC[t][n];
        }
        float z = xz[(size_t)m * (2 * DI) + DI + d];
        float sg = 1.0f / (1.0f + expf(-z));
        ym[(size_t)m * DI + d] = rndtf((y + dskip * xv) * (z * sg));
    }
}

// ---------------- mask -------------------------------------------------------
__global__ void k_mask(float* __restrict__ X, const int* __restrict__ len,
                       float* __restrict__ out2) {
    int idx = blockIdx.x * 256 + threadIdx.x;
    int m = idx >> 10;
    int b = m >> 11;
    int t = m & (TSEQ - 1);
    float v = X[idx];
    v = (t < len[b]) ? v : 0.f;
    X[idx] = v;
    if (out2) out2[idx] = v;
}

// ---------------- host orchestration ----------------------------------------
static void launch_gemm(const float* A, const float* Wsrc, float* wscr, float* C,
                        const float* bias, int N, int K, int lda, int ldc, int epi) {
    k_round<<<(N * K / 4 + 255) / 256, 256>>>(Wsrc, wscr, N * K / 4);
    dim3 grid((N + 255) / 256, MROWS / 128);
    k_gemm_tc<<<grid, 256, SMEM6>>>(A, wscr, C, bias, N, K, lda, K, ldc, epi);
}

extern "C" void kernel_launch(void* const* d_in, const int* in_sizes, int n_in,
                              void* d_out, int out_size) {
    const float* x       = (const float*)d_in[0];
    const int*   lengths = (const int*)  d_in[1];
    const float* ln0_g   = (const float*)d_in[2];
    const float* ln0_b   = (const float*)d_in[3];
    const float* ln1_g   = (const float*)d_in[4];
    const float* ln1_b   = (const float*)d_in[5];
    const float* in_w    = (const float*)d_in[6];
    const float* conv_w  = (const float*)d_in[7];
    const float* conv_b  = (const float*)d_in[8];
    const float* xp_w    = (const float*)d_in[9];
    const float* dt_w    = (const float*)d_in[10];
    const float* dt_b    = (const float*)d_in[11];
    const float* A_log   = (const float*)d_in[12];
    const float* D_skip  = (const float*)d_in[13];
    const float* out_w   = (const float*)d_in[14];
    const float* ln2_g   = (const float*)d_in[15];
    const float* ln2_b   = (const float*)d_in[16];
    const float* f1_w    = (const float*)d_in[17];
    const float* f1_b    = (const float*)d_in[18];
    const float* f2_w    = (const float*)d_in[19];
    const float* f2_b    = (const float*)d_in[20];

    cudaFuncSetAttribute(k_gemm_tc, cudaFuncAttributeMaxDynamicSharedMemorySize, SMEM6);

    float *pX, *pXn, *pXz, *pXc, *pXd, *pDt, *pY, *pF, *pP, *pS, *pI, *pWa;
    cudaGetSymbolAddress((void**)&pX,  g_X);
    cudaGetSymbolAddress((void**)&pXn, g_Xn);
    cudaGetSymbolAddress((void**)&pXz, g_xz);
    cudaGetSymbolAddress((void**)&pXc, g_xc);
    cudaGetSymbolAddress((void**)&pXd, g_xd);
    cudaGetSymbolAddress((void**)&pDt, g_dt);
    cudaGetSymbolAddress((void**)&pY,  g_ym);
    cudaGetSymbolAddress((void**)&pF,  g_ffn);
    cudaGetSymbolAddress((void**)&pP,  g_cP);
    cudaGetSymbolAddress((void**)&pS,  g_cS);
    cudaGetSymbolAddress((void**)&pI,  g_cI);
    cudaGetSymbolAddress((void**)&pWa, g_wa);

    k_add_pe<<<(MROWS * DM) / 256, 256>>>(x, pX);
    k_ln<<<MROWS, 256>>>(pX, pX, ln0_g, ln0_b, 0);

    for (int i = 0; i < 4; i++) {
        // --- Mamba block ---
        k_ln<<<MROWS, 256>>>(pX, pXn, ln1_g + i * DM, ln1_b + i * DM, 1);
        launch_gemm(pXn, in_w + (size_t)i * 2 * DI * DM, pWa, pXz, nullptr,
                    2 * DI, DM, DM, 2 * DI, 0);
        k_conv<<<(MROWS * DI) / 256, 256>>>(pXz, conv_w + (size_t)i * DI * 4,
                                            conv_b + (size_t)i * DI, pXc);
        launch_gemm(pXc, xp_w + (size_t)i * 96 * DI, pWa, pXd, nullptr,
                    96, DI, DI, 96, 6);           // rounded store (feeds dt GEMM)
        launch_gemm(pXd, dt_w + (size_t)i * DI * DTR, pWa, pDt, dt_b + (size_t)i * DI,
                    DI, DTR, 96, DI, 5);          // softplus
        dim3 sg(DI / 256, NC, BB);
        k_scanA<<<sg, 256>>>(pDt, pXc, pXd, A_log + (size_t)i * DI * DS_, pP, pS);
        k_scanB<<<(BB * DI) / 256, 256>>>(pP, pS, pI);
        k_scanC<<<sg, 256>>>(pDt, pXc, pXd, pXz, A_log + (size_t)i * DI * DS_,
                             D_skip + (size_t)i * DI, pI, pY);
        launch_gemm(pY, out_w + (size_t)i * DM * DI, pWa, pX, nullptr,
                    DM, DI, DI, DM, 3);           // residual add
        // --- FFN block ---
        k_ln<<<MROWS, 256>>>(pX, pXn, ln2_g + i * DM, ln2_b + i * DM, 1);
        launch_gemm(pXn, f1_w + (size_t)i * FFND * DM, pWa, pF, f1_b + (size_t)i * FFND,
                    FFND, DM, DM, FFND, 2);       // gelu (rounded)
        launch_gemm(pF, f2_w + (size_t)i * DM * FFND, pWa, pX, f2_b + (size_t)i * DM,
                    DM, FFND, FFND, DM, 4);       // residual + bias
        k_mask<<<(MROWS * DM) / 256, 256>>>(pX, lengths,
                                            (i == 3) ? (float*)d_out : nullptr);
    }
}

// round 7
// speedup vs baseline: 1.8207x; 1.8207x over previous
#include <cuda_runtime.h>
#include <cuda_fp16.h>
#include <stdint.h>
#include <math.h>

#define BB    4
#define TSEQ  2048
#define DM    1024
#define DI    2048
#define DS_   16
#define DTR   64
#define FFND  3584
#define MROWS (BB*TSEQ)   // 8192
#define NC    64
#define CL    32

// ---------------- static device scratch -----------------------------------
__device__ float  g_X  [MROWS*DM];       // residual stream (fp32)
__device__ __half g_Xn [MROWS*DM];       // LN output (GEMM input)
__device__ float  g_xz [MROWS*2*DI];     // in_proj output
__device__ __half g_xc [MROWS*DI];       // conv+silu output (GEMM+scan input)
__device__ __half g_xd [MROWS*96];       // x_proj output (dt|B|C)
__device__ float  g_dt [MROWS*DI];       // softplus(dt)
__device__ __half g_ym [MROWS*DI];       // gated scan output (GEMM input)
__device__ __half g_ffn[MROWS*FFND];     // ffn hidden (GEMM input)
__device__ float  g_cP [BB*NC*DI*DS_];
__device__ float  g_cS [BB*NC*DI*DS_];
__device__ float  g_cI [BB*NC*DI*DS_];
__device__ __half g_wa [4*1024*1024];    // f16 weight scratch (largest: 4M)

// ---------------- helpers ---------------------------------------------------
__device__ __forceinline__ void cpasync16(uint32_t dst, const void* src) {
    asm volatile("cp.async.ca.shared.global [%0], [%1], 16;" :: "r"(dst), "l"(src));
}
#define LDSM4(r0, r1, r2, r3, a) \
    asm volatile("ldmatrix.sync.aligned.m8n8.x4.shared.b16 {%0,%1,%2,%3}, [%4];" \
        : "=r"(r0), "=r"(r1), "=r"(r2), "=r"(r3) : "r"(a))
__device__ __forceinline__ void mma_f16(float c[4], uint32_t a0, uint32_t a1,
                                        uint32_t a2, uint32_t a3,
                                        uint32_t b0, uint32_t b1) {
    asm volatile(
        "mma.sync.aligned.m16n8k16.row.col.f32.f16.f16.f32 "
        "{%0,%1,%2,%3}, {%4,%5,%6,%7}, {%8,%9}, {%0,%1,%2,%3};"
        : "+f"(c[0]), "+f"(c[1]), "+f"(c[2]), "+f"(c[3])
        : "r"(a0), "r"(a1), "r"(a2), "r"(a3), "r"(b0), "r"(b1));
}

// ---------------- weight convert f32 -> f16 ---------------------------------
__global__ void k_round(const float* __restrict__ in, __half* __restrict__ out, int n4) {
    int i = blockIdx.x * 256 + threadIdx.x;
    if (i < n4) {
        float4 v = ((const float4*)in)[i];
        __half2 h0 = __floats2half2_rn(v.x, v.y);
        __half2 h1 = __floats2half2_rn(v.z, v.w);
        ((uint2*)out)[i] = make_uint2(*(uint32_t*)&h0, *(uint32_t*)&h1);
    }
}

// ---------------- positional encoding ---------------------------------------
__global__ void k_add_pe(const float* __restrict__ xin, float* __restrict__ X) {
    int idx = blockIdx.x * 256 + threadIdx.x;
    int d = idx & (DM - 1);
    int m = idx >> 10;
    int t = m & (TSEQ - 1);
    int p2 = d & ~1;
    float freq = expf((float)p2 * (-9.210340371976184f / (float)DM));
    float ang = (float)t * freq;
    float pe = (d & 1) ? cosf(ang) : sinf(ang);
    X[idx] = xin[idx] + pe;
}

// ---------------- layernorm --------------------------------------------------
__device__ __forceinline__ float blockReduce(float v, float* sh) {
    int lane = threadIdx.x & 31, wid = threadIdx.x >> 5;
    #pragma unroll
    for (int o = 16; o > 0; o >>= 1) v += __shfl_down_sync(0xffffffffu, v, o);
    if (lane == 0) sh[wid] = v;
    __syncthreads();
    if (threadIdx.x == 0) {
        float s = 0.f;
        #pragma unroll
        for (int i = 0; i < 8; i++) s += sh[i];
        sh[32] = s;
    }
    __syncthreads();
    float r = sh[32];
    __syncthreads();
    return r;
}

// fp32-out LN (layer-0 prenorm, in place)
__global__ __launch_bounds__(256) void k_ln(const float* __restrict__ in,
                                            float* __restrict__ out,
                                            const float* __restrict__ g,
                                            const float* __restrict__ b) {
    __shared__ float sh[33];
    int row = blockIdx.x;
    float4 v = ((const float4*)(in + (size_t)row * DM))[threadIdx.x];
    float mean = blockReduce(v.x + v.y + v.z + v.w, sh) * (1.0f / DM);
    float dx = v.x - mean, dy = v.y - mean, dz = v.z - mean, dw = v.w - mean;
    float var = blockReduce(dx*dx + dy*dy + dz*dz + dw*dw, sh) * (1.0f / DM);
    float rstd = rsqrtf(var + 1e-5f);
    int c = threadIdx.x * 4;
    float4 o;
    o.x = dx * rstd * g[c + 0] + b[c + 0];
    o.y = dy * rstd * g[c + 1] + b[c + 1];
    o.z = dz * rstd * g[c + 2] + b[c + 2];
    o.w = dw * rstd * g[c + 3] + b[c + 3];
    ((float4*)(out + (size_t)row * DM))[threadIdx.x] = o;
}

// f16-out LN (GEMM inputs)
__global__ __launch_bounds__(256) void k_ln_h(const float* __restrict__ in,
                                              __half* __restrict__ out,
                                              const float* __restrict__ g,
                                              const float* __restrict__ b) {
    __shared__ float sh[33];
    int row = blockIdx.x;
    float4 v = ((const float4*)(in + (size_t)row * DM))[threadIdx.x];
    float mean = blockReduce(v.x + v.y + v.z + v.w, sh) * (1.0f / DM);
    float dx = v.x - mean, dy = v.y - mean, dz = v.z - mean, dw = v.w - mean;
    float var = blockReduce(dx*dx + dy*dy + dz*dz + dw*dw, sh) * (1.0f / DM);
    float rstd = rsqrtf(var + 1e-5f);
    int c = threadIdx.x * 4;
    __half2 h0 = __floats2half2_rn(dx * rstd * g[c+0] + b[c+0], dy * rstd * g[c+1] + b[c+1]);
    __half2 h1 = __floats2half2_rn(dz * rstd * g[c+2] + b[c+2], dw * rstd * g[c+3] + b[c+3]);
    ((uint2*)(out + (size_t)row * DM))[threadIdx.x] = make_uint2(*(uint32_t*)&h0, *(uint32_t*)&h1);
}

// ---------------- fp16 tensor-core GEMM --------------------------------------
// C[m,n] = sum_k A[m,k]*W[n,k]; A,W are f16; accumulate f32.
// CTA 128x128, 256 thr, 8 warps (2x4), warp tile 64x32; BK=32 halves.
// epi: 0:Cf=v  2:Ch=gelu(v+bias)  3:Cf+=v  4:Cf+=v+bias  5:Cf=softplus(v+bias)  6:Ch=v
#define SROWH 40                         // halves per smem row (80 B, conflict-free)
#define BUFB  (128 * SROWH * 2)          // bytes per buffer (10240)

__global__ __launch_bounds__(256, 2) void k_gemm_tc(
    const __half* __restrict__ A, const __half* __restrict__ W,
    float* __restrict__ Cf, __half* __restrict__ Ch, const float* __restrict__ bias,
    int N, int K, int lda, int ldw, int ldc, int epi) {
    __shared__ __half smh[4 * 128 * SROWH];   // A[2] then B[2], 40 KB
    const int tid = threadIdx.x;
    const int lane = tid & 31;
    const int wid = tid >> 5;
    const int wm = wid & 1, wn = wid >> 1;
    const int g = lane >> 2, tig = lane & 3;
    const int bM = blockIdx.y * 128, bN = blockIdx.x * 128;

    // loaders: thread -> (row, 2 chunks of 16B)
    const int lrow = tid >> 1;
    const int lc0 = (tid & 1) << 1;          // chunk 0/1 or 2/3
    const __half* Ag = A + (size_t)(bM + lrow) * lda;
    int wr = bN + lrow; if (wr >= N) wr = N - 1;
    const __half* Wg = W + (size_t)wr * ldw;

    const uint32_t sA = (uint32_t)__cvta_generic_to_shared(smh);
    const uint32_t sB = sA + 2 * BUFB;
    const uint32_t dRow = (uint32_t)lrow * (SROWH * 2);

    // ldmatrix lane address offsets (bytes within buffer)
    const uint32_t aoff = (uint32_t)((wm * 64 + (lane & 15)) * (SROWH * 2) + ((lane >> 4) << 3) * 2);
    const uint32_t boff = (uint32_t)((wn * 32 + ((lane >> 4) << 3) + (lane & 7)) * (SROWH * 2)
                                     + (((lane >> 3) & 1) << 3) * 2);

    float acc[4][4][4];
    #pragma unroll
    for (int i = 0; i < 4; i++)
        #pragma unroll
        for (int j = 0; j < 4; j++)
            #pragma unroll
            for (int q = 0; q < 4; q++) acc[i][j][q] = 0.f;

    const int KT = K / 32;
    #pragma unroll
    for (int c = 0; c < 2; c++) {
        cpasync16(sA + dRow + (lc0 + c) * 16, Ag + (lc0 + c) * 8);
        cpasync16(sB + dRow + (lc0 + c) * 16, Wg + (lc0 + c) * 8);
    }
    asm volatile("cp.async.commit_group;");

    for (int kt = 0; kt < KT; kt++) {
        const int buf = kt & 1;
        if (kt + 1 < KT) {
            const int nb = buf ^ 1;
            const int k2 = (kt + 1) * 32;
            #pragma unroll
            for (int c = 0; c < 2; c++) {
                cpasync16(sA + nb * BUFB + dRow + (lc0 + c) * 16, Ag + k2 + (lc0 + c) * 8);
                cpasync16(sB + nb * BUFB + dRow + (lc0 + c) * 16, Wg + k2 + (lc0 + c) * 8);
            }
            asm volatile("cp.async.commit_group;");
            asm volatile("cp.async.wait_group 1;");
        } else {
            asm volatile("cp.async.wait_group 0;");
        }
        __syncthreads();

        const uint32_t ab = sA + buf * BUFB;
        const uint32_t bb = sB + buf * BUFB;
        #pragma unroll
        for (int ks = 0; ks < 2; ks++) {
            uint32_t af[4][4], bf[4][2];
            #pragma unroll
            for (int i = 0; i < 4; i++)
                LDSM4(af[i][0], af[i][1], af[i][2], af[i][3],
                      ab + aoff + (uint32_t)(i * 16 * SROWH * 2 + ks * 32));
            #pragma unroll
            for (int jp = 0; jp < 2; jp++)
                LDSM4(bf[2*jp][0], bf[2*jp][1], bf[2*jp+1][0], bf[2*jp+1][1],
                      bb + boff + (uint32_t)(jp * 16 * SROWH * 2 + ks * 32));
            #pragma unroll
            for (int i = 0; i < 4; i++)
                #pragma unroll
                for (int j = 0; j < 4; j++)
                    mma_f16(acc[i][j], af[i][0], af[i][1], af[i][2], af[i][3],
                            bf[j][0], bf[j][1]);
        }
        __syncthreads();
    }

    // epilogue
    #pragma unroll
    for (int i = 0; i < 4; i++) {
        const int r0 = bM + wm * 64 + i * 16 + g;
        #pragma unroll
        for (int j = 0; j < 4; j++) {
            const int cn = bN + wn * 32 + j * 8 + tig * 2;
            #pragma unroll
            for (int q = 0; q < 4; q++) {
                const int r = r0 + (q >> 1) * 8;
                const int c = cn + (q & 1);
                if (c >= N) continue;
                float v = acc[i][j][q];
                if (epi == 0) { Cf[(size_t)r * ldc + c] = v; }
                else if (epi == 2) {
                    float u = v + bias[c];
                    Ch[(size_t)r * ldc + c] =
                        __float2half_rn(0.5f * u * (1.0f + erff(u * 0.70710678118654752f)));
                } else if (epi == 3) { Cf[(size_t)r * ldc + c] += v; }
                else if (epi == 4) { Cf[(size_t)r * ldc + c] += v + bias[c]; }
                else if (epi == 5) {
                    float u = v + bias[c];
                    Cf[(size_t)r * ldc + c] = (u > 20.f) ? u : log1pf(expf(u));
                } else { Ch[(size_t)r * ldc + c] = __float2half_rn(v); }
            }
        }
    }
}

// ---------------- causal depthwise conv (k=4) + silu -------------------------
__global__ void k_conv(const float* __restrict__ xz, const float* __restrict__ cw,
                       const float* __restrict__ cb, __half* __restrict__ xc) {
    int idx = blockIdx.x * 256 + threadIdx.x;
    int d = idx & (DI - 1);
    int m = idx >> 11;
    int t = m & (TSEQ - 1);
    float acc = cb[d];
    #pragma unroll
    for (int k = 0; k < 4; k++) {
        int tt = t + k - 3;
        if (tt >= 0) acc += xz[(size_t)(m + k - 3) * (2 * DI) + d] * cw[d * 4 + k];
    }
    float sg = 1.0f / (1.0f + expf(-acc));
    xc[idx] = __float2half_rn(acc * sg);
}

// ---------------- scan pass A -------------------------------------------------
__global__ __launch_bounds__(256) void k_scanA(
    const float* __restrict__ dt, const __half* __restrict__ xc,
    const __half* __restrict__ xd, const float* __restrict__ Alog,
    float* __restrict__ gP, float* __restrict__ gS) {
    __shared__ float shB[CL][DS_];
    int b = blockIdx.z, c = blockIdx.y;
    int d = blockIdx.x * 256 + threadIdx.x;
    int mbase = b * TSEQ + c * CL;
    for (int idx = threadIdx.x; idx < CL * DS_; idx += 256) {
        int t = idx >> 4, col = idx & 15;
        shB[t][col] = __half2float(xd[(size_t)(mbase + t) * 96 + 64 + col]);
    }
    __syncthreads();
    float r[DS_];
    bool fast = true;
    #pragma unroll
    for (int n = 0; n < DS_; n++) {
        r[n] = expf(Alog[(size_t)d * DS_ + n]);
        fast = fast && (fabsf(r[n] - (float)(n + 1)) < 1e-3f * (float)(n + 1));
    }
    float P[DS_], S[DS_];
    #pragma unroll
    for (int n = 0; n < DS_; n++) { P[n] = 1.f; S[n] = 0.f; }
    for (int t = 0; t < CL; t++) {
        int m = mbase + t;
        float dv = dt[(size_t)m * DI + d];
        float xv = __half2float(xc[(size_t)m * DI + d]);
        float u = xv * dv;
        float dA[DS_];
        if (fast) {
            float e = expf(-dv);
            float p = 1.f;
            #pragma unroll
            for (int n = 0; n < DS_; n++) { p *= e; dA[n] = p; }
        } else {
            #pragma unroll
            for (int n = 0; n < DS_; n++) dA[n] = expf(-dv * r[n]);
        }
        #pragma unroll
        for (int n = 0; n < DS_; n++) {
            S[n] = S[n] * dA[n] + u * shB[t][n];
            P[n] *= dA[n];
        }
    }
    size_t base = (((size_t)b * NC + c) * DI + d) * DS_;
    #pragma unroll
    for (int n = 0; n < DS_; n += 4) {
        *(float4*)(gP + base + n) = make_float4(P[n], P[n+1], P[n+2], P[n+3]);
        *(float4*)(gS + base + n) = make_float4(S[n], S[n+1], S[n+2], S[n+3]);
    }
}

// ---------------- scan pass B -------------------------------------------------
__global__ void k_scanB(const float* __restrict__ gP, const float* __restrict__ gS,
                        float* __restrict__ gI) {
    int idx = blockIdx.x * 256 + threadIdx.x;
    int b = idx >> 11, d = idx & (DI - 1);
    float s[DS_];
    #pragma unroll
    for (int n = 0; n < DS_; n++) s[n] = 0.f;
    for (int c = 0; c < NC; c++) {
        size_t base = (((size_t)b * NC + c) * DI + d) * DS_;
        #pragma unroll
        for (int n = 0; n < DS_; n += 4)
            *(float4*)(gI + base + n) = make_float4(s[n], s[n+1], s[n+2], s[n+3]);
        #pragma unroll
        for (int n = 0; n < DS_; n += 4) {
            float4 P = *(const float4*)(gP + base + n);
            float4 S = *(const float4*)(gS + base + n);
            s[n+0] = s[n+0] * P.x + S.x;
            s[n+1] = s[n+1] * P.y + S.y;
            s[n+2] = s[n+2] * P.z + S.z;
            s[n+3] = s[n+3] * P.w + S.w;
        }
    }
}

// ---------------- scan pass C -------------------------------------------------
__global__ __launch_bounds__(256) void k_scanC(
    const float* __restrict__ dt, const __half* __restrict__ xc,
    const __half* __restrict__ xd, const float* __restrict__ xz,
    const float* __restrict__ Alog, const float* __restrict__ Dsk,
    const float* __restrict__ gI, __half* __restrict__ ym) {
    __shared__ float shB[CL][DS_];
    __shared__ float shC[CL][DS_];
    int b = blockIdx.z, c = blockIdx.y;
    int d = blockIdx.x * 256 + threadIdx.x;
    int mbase = b * TSEQ + c * CL;
    for (int idx = threadIdx.x; idx < CL * 32; idx += 256) {
        int t = idx >> 5, col = idx & 31;
        float v = __half2float(xd[(size_t)(mbase + t) * 96 + 64 + col]);
        if (col < 16) shB[t][col] = v;
        else shC[t][col - 16] = v;
    }
    __syncthreads();
    float r[DS_];
    bool fast = true;
    #pragma unroll
    for (int n = 0; n < DS_; n++) {
        r[n] = expf(Alog[(size_t)d * DS_ + n]);
        fast = fast && (fabsf(r[n] - (float)(n + 1)) < 1e-3f * (float)(n + 1));
    }
    float dskip = Dsk[d];
    float s[DS_];
    size_t base = (((size_t)b * NC + c) * DI + d) * DS_;
    #pragma unroll
    for (int n = 0; n < DS_; n += 4) {
        float4 v = *(const float4*)(gI + base + n);
        s[n+0] = v.x; s[n+1] = v.y; s[n+2] = v.z; s[n+3] = v.w;
    }
    for (int t = 0; t < CL; t++) {
        int m = mbase + t;
        float dv = dt[(size_t)m * DI + d];
        float xv = __half2float(xc[(size_t)m * DI + d]);
        float u = xv * dv;
        float dA[DS_];
        if (fast) {
            float e = expf(-dv);
            float p = 1.f;
            #pragma unroll
            for (int n = 0; n < DS_; n++) { p *= e; dA[n] = p; }
        } else {
            #pragma unroll
            for (int n = 0; n < DS_; n++) dA[n] = expf(-dv * r[n]);
        }
        float y = 0.f;
        #pragma unroll
        for (int n = 0; n < DS_; n++) {
            s[n] = s[n] * dA[n] + u * shB[t][n];
            y += s[n] * shC[t][n];
        }
        float z = xz[(size_t)m * (2 * DI) + DI + d];
        float sg = 1.0f / (1.0f + expf(-z));
        ym[(size_t)m * DI + d] = __float2half_rn((y + dskip * xv) * (z * sg));
    }
}

// ---------------- mask ---------------------------------------------------------
__global__ void k_mask(float* __restrict__ X, const int* __restrict__ len,
                       float* __restrict__ out2) {
    int idx = blockIdx.x * 256 + threadIdx.x;
    int m = idx >> 10;
    int b = m >> 11;
    int t = m & (TSEQ - 1);
    float v = X[idx];
    v = (t < len[b]) ? v : 0.f;
    X[idx] = v;
    if (out2) out2[idx] = v;
}

// ---------------- host orchestration -------------------------------------------
static void launch_gemm(const __half* A, const float* Wsrc, __half* wscr,
                        float* Cf, __half* Ch, const float* bias,
                        int N, int K, int lda, int ldc, int epi) {
    k_round<<<(N * K / 4 + 255) / 256, 256>>>(Wsrc, wscr, N * K / 4);
    dim3 grid((N + 127) / 128, MROWS / 128);
    k_gemm_tc<<<grid, 256>>>(A, wscr, Cf, Ch, bias, N, K, lda, K, ldc, epi);
}

extern "C" void kernel_launch(void* const* d_in, const int* in_sizes, int n_in,
                              void* d_out, int out_size) {
    const float* x       = (const float*)d_in[0];
    const int*   lengths = (const int*)  d_in[1];
    const float* ln0_g   = (const float*)d_in[2];
    const float* ln0_b   = (const float*)d_in[3];
    const float* ln1_g   = (const float*)d_in[4];
    const float* ln1_b   = (const float*)d_in[5];
    const float* in_w    = (const float*)d_in[6];
    const float* conv_w  = (const float*)d_in[7];
    const float* conv_b  = (const float*)d_in[8];
    const float* xp_w    = (const float*)d_in[9];
    const float* dt_w    = (const float*)d_in[10];
    const float* dt_b    = (const float*)d_in[11];
    const float* A_log   = (const float*)d_in[12];
    const float* D_skip  = (const float*)d_in[13];
    const float* out_w   = (const float*)d_in[14];
    const float* ln2_g   = (const float*)d_in[15];
    const float* ln2_b   = (const float*)d_in[16];
    const float* f1_w    = (const float*)d_in[17];
    const float* f1_b    = (const float*)d_in[18];
    const float* f2_w    = (const float*)d_in[19];
    const float* f2_b    = (const float*)d_in[20];

    float *pX, *pXz, *pDt, *pP, *pS, *pI;
    __half *pXn, *pXc, *pXd, *pY, *pF, *pWa;
    cudaGetSymbolAddress((void**)&pX,  g_X);
    cudaGetSymbolAddress((void**)&pXn, g_Xn);
    cudaGetSymbolAddress((void**)&pXz, g_xz);
    cudaGetSymbolAddress((void**)&pXc, g_xc);
    cudaGetSymbolAddress((void**)&pXd, g_xd);
    cudaGetSymbolAddress((void**)&pDt, g_dt);
    cudaGetSymbolAddress((void**)&pY,  g_ym);
    cudaGetSymbolAddress((void**)&pF,  g_ffn);
    cudaGetSymbolAddress((void**)&pP,  g_cP);
    cudaGetSymbolAddress((void**)&pS,  g_cS);
    cudaGetSymbolAddress((void**)&pI,  g_cI);
    cudaGetSymbolAddress((void**)&pWa, g_wa);

    k_add_pe<<<(MROWS * DM) / 256, 256>>>(x, pX);
    k_ln<<<MROWS, 256>>>(pX, pX, ln0_g, ln0_b);

    for (int i = 0; i < 4; i++) {
        // --- Mamba block ---
        k_ln_h<<<MROWS, 256>>>(pX, pXn, ln1_g + i * DM, ln1_b + i * DM);
        launch_gemm(pXn, in_w + (size_t)i * 2 * DI * DM, pWa, pXz, nullptr, nullptr,
                    2 * DI, DM, DM, 2 * DI, 0);
        k_conv<<<(MROWS * DI) / 256, 256>>>(pXz, conv_w + (size_t)i * DI * 4,
                                            conv_b + (size_t)i * DI, pXc);
        launch_gemm(pXc, xp_w + (size_t)i * 96 * DI, pWa, nullptr, pXd, nullptr,
                    96, DI, DI, 96, 6);            // store half
        launch_gemm(pXd, dt_w + (size_t)i * DI * DTR, pWa, pDt, nullptr,
                    dt_b + (size_t)i * DI, DI, DTR, 96, DI, 5);  // softplus
        dim3 sg(DI / 256, NC, BB);
        k_scanA<<<sg, 256>>>(pDt, pXc, pXd, A_log + (size_t)i * DI * DS_, pP, pS);
        k_scanB<<<(BB * DI) / 256, 256>>>(pP, pS, pI);
        k_scanC<<<sg, 256>>>(pDt, pXc, pXd, pXz, A_log + (size_t)i * DI * DS_,
                             D_skip + (size_t)i * DI, pI, pY);
        launch_gemm(pY, out_w + (size_t)i * DM * DI, pWa, pX, nullptr, nullptr,
                    DM, DI, DI, DM, 3);            // residual add
        // --- FFN block ---
        k_ln_h<<<MROWS, 256>>>(pX, pXn, ln2_g + i * DM, ln2_b + i * DM);
        launch_gemm(pXn, f1_w + (size_t)i * FFND * DM, pWa, nullptr, pF,
                    f1_b + (size_t)i * FFND, FFND, DM, DM, FFND, 2);  // gelu->half
        launch_gemm(pF, f2_w + (size_t)i * DM * FFND, pWa, pX, nullptr,
                    f2_b + (size_t)i * DM, DM, FFND, FFND, DM, 4);    // resid+bias
        k_mask<<<(MROWS * DM) / 256, 256>>>(pX, lengths,
                                            (i == 3) ? (float*)d_out : nullptr);
    }
}

// round 8
// speedup vs baseline: 1.8717x; 1.0281x over previous
#include <cuda_runtime.h>
#include <cuda_fp16.h>
#include <stdint.h>
#include <math.h>

#define BB    4
#define TSEQ  2048
#define DM    1024
#define DI    2048
#define DS_   16
#define DTR   64
#define FFND  3584
#define MROWS (BB*TSEQ)   // 8192
#define NC    64
#define CL    32

// ---------------- static device scratch -----------------------------------
__device__ float  g_X  [MROWS*DM];       // residual stream (fp32)
__device__ __half g_Xn [MROWS*DM];       // LN output
__device__ __half g_xz [MROWS*2*DI];     // in_proj output (half)
__device__ __half g_xc [MROWS*DI];       // conv+silu output
__device__ __half g_xd [MROWS*96];       // x_proj output (dt|B|C)
__device__ __half g_dt [MROWS*DI];       // softplus(dt) (half)
__device__ __half g_ym [MROWS*DI];       // gated scan output
__device__ __half g_ffn[MROWS*FFND];     // ffn hidden
__device__ float  g_cP [BB*NC*DI*DS_];
__device__ float  g_cS [BB*NC*DI*DS_];
__device__ float  g_cI [BB*NC*DI*DS_];
__device__ __half g_wa [56*1024*1024];   // all weights, f16 (112 MB)

// weight scratch offsets (halves)
#define OW_IN   0
#define SZ_IN   (4*2*DI*DM)              // 16.78M
#define OW_XP   (OW_IN + SZ_IN)
#define SZ_XP   (4*96*DI)
#define OW_DT   (OW_XP + SZ_XP)
#define SZ_DT   (4*DI*DTR)
#define OW_OUT  (OW_DT + SZ_DT)
#define SZ_OUT  (4*DM*DI)
#define OW_F1   (OW_OUT + SZ_OUT)
#define SZ_F1   (4*FFND*DM)
#define OW_F2   (OW_F1 + SZ_F1)
#define SZ_F2   (4*DM*FFND)

// ---------------- helpers ---------------------------------------------------
__device__ __forceinline__ void cpasync16(uint32_t dst, const void* src) {
    asm volatile("cp.async.ca.shared.global [%0], [%1], 16;" :: "r"(dst), "l"(src));
}
#define LDSM4(r0, r1, r2, r3, a) \
    asm volatile("ldmatrix.sync.aligned.m8n8.x4.shared.b16 {%0,%1,%2,%3}, [%4];" \
        : "=r"(r0), "=r"(r1), "=r"(r2), "=r"(r3) : "r"(a))
__device__ __forceinline__ void mma_f16(float c[4], uint32_t a0, uint32_t a1,
                                        uint32_t a2, uint32_t a3,
                                        uint32_t b0, uint32_t b1) {
    asm volatile(
        "mma.sync.aligned.m16n8k16.row.col.f32.f16.f16.f32 "
        "{%0,%1,%2,%3}, {%4,%5,%6,%7}, {%8,%9}, {%0,%1,%2,%3};"
        : "+f"(c[0]), "+f"(c[1]), "+f"(c[2]), "+f"(c[3])
        : "r"(a0), "r"(a1), "r"(a2), "r"(a3), "r"(b0), "r"(b1));
}

// ---------------- weight convert f32 -> f16 ---------------------------------
__global__ void k_round(const float* __restrict__ in, __half* __restrict__ out, int n4) {
    int i = blockIdx.x * 256 + threadIdx.x;
    if (i < n4) {
        float4 v = ((const float4*)in)[i];
        __half2 h0 = __floats2half2_rn(v.x, v.y);
        __half2 h1 = __floats2half2_rn(v.z, v.w);
        ((uint2*)out)[i] = make_uint2(*(uint32_t*)&h0, *(uint32_t*)&h1);
    }
}

// ---------------- positional encoding ---------------------------------------
__global__ void k_add_pe(const float* __restrict__ xin, float* __restrict__ X) {
    int idx = blockIdx.x * 256 + threadIdx.x;
    int d = idx & (DM - 1);
    int m = idx >> 10;
    int t = m & (TSEQ - 1);
    int p2 = d & ~1;
    float freq = expf((float)p2 * (-9.210340371976184f / (float)DM));
    float ang = (float)t * freq;
    float pe = (d & 1) ? cosf(ang) : sinf(ang);
    X[idx] = xin[idx] + pe;
}

// ---------------- layernorm --------------------------------------------------
__device__ __forceinline__ float blockReduce(float v, float* sh) {
    int lane = threadIdx.x & 31, wid = threadIdx.x >> 5;
    #pragma unroll
    for (int o = 16; o > 0; o >>= 1) v += __shfl_down_sync(0xffffffffu, v, o);
    if (lane == 0) sh[wid] = v;
    __syncthreads();
    if (threadIdx.x == 0) {
        float s = 0.f;
        #pragma unroll
        for (int i = 0; i < 8; i++) s += sh[i];
        sh[32] = s;
    }
    __syncthreads();
    float r = sh[32];
    __syncthreads();
    return r;
}

__global__ __launch_bounds__(256) void k_ln(const float* __restrict__ in,
                                            float* __restrict__ out,
                                            const float* __restrict__ g,
                                            const float* __restrict__ b) {
    __shared__ float sh[33];
    int row = blockIdx.x;
    float4 v = ((const float4*)(in + (size_t)row * DM))[threadIdx.x];
    float mean = blockReduce(v.x + v.y + v.z + v.w, sh) * (1.0f / DM);
    float dx = v.x - mean, dy = v.y - mean, dz = v.z - mean, dw = v.w - mean;
    float var = blockReduce(dx*dx + dy*dy + dz*dz + dw*dw, sh) * (1.0f / DM);
    float rstd = rsqrtf(var + 1e-5f);
    int c = threadIdx.x * 4;
    float4 o;
    o.x = dx * rstd * g[c + 0] + b[c + 0];
    o.y = dy * rstd * g[c + 1] + b[c + 1];
    o.z = dz * rstd * g[c + 2] + b[c + 2];
    o.w = dw * rstd * g[c + 3] + b[c + 3];
    ((float4*)(out + (size_t)row * DM))[threadIdx.x] = o;
}

__global__ __launch_bounds__(256) void k_ln_h(const float* __restrict__ in,
                                              __half* __restrict__ out,
                                              const float* __restrict__ g,
                                              const float* __restrict__ b) {
    __shared__ float sh[33];
    int row = blockIdx.x;
    float4 v = ((const float4*)(in + (size_t)row * DM))[threadIdx.x];
    float mean = blockReduce(v.x + v.y + v.z + v.w, sh) * (1.0f / DM);
    float dx = v.x - mean, dy = v.y - mean, dz = v.z - mean, dw = v.w - mean;
    float var = blockReduce(dx*dx + dy*dy + dz*dz + dw*dw, sh) * (1.0f / DM);
    float rstd = rsqrtf(var + 1e-5f);
    int c = threadIdx.x * 4;
    __half2 h0 = __floats2half2_rn(dx * rstd * g[c+0] + b[c+0], dy * rstd * g[c+1] + b[c+1]);
    __half2 h1 = __floats2half2_rn(dz * rstd * g[c+2] + b[c+2], dw * rstd * g[c+3] + b[c+3]);
    ((uint2*)(out + (size_t)row * DM))[threadIdx.x] = make_uint2(*(uint32_t*)&h0, *(uint32_t*)&h1);
}

// ---------------- fp16 tensor-core GEMM --------------------------------------
// C[m,n] = sum_k A[m,k]*W[n,k]; CTA 128x128, 8 warps (2x4), warp 64x32, BK=64.
// epi: 0:Cf=v 2:Ch=gelu(v+b) 3:Cf+=v 5:Ch=softplus(v+b) 6:Ch=v
//      7:Cf=(Cf+v+b)*mask (+out2 copy)
#define SROWH 72                           // halves per smem row (144 B)
#define BUFB  (128 * SROWH * 2)            // 18432 B per buffer
#define SMEM8 (4 * BUFB)                   // 73728 B

__global__ __launch_bounds__(256, 2) void k_gemm_tc(
    const __half* __restrict__ A, const __half* __restrict__ W,
    float* __restrict__ Cf, __half* __restrict__ Ch, const float* __restrict__ bias,
    const int* __restrict__ lenp, float* __restrict__ out2,
    int N, int K, int lda, int ldw, int ldc, int epi) {
    extern __shared__ __half smh[];
    const int tid = threadIdx.x;
    const int lane = tid & 31;
    const int wid = tid >> 5;
    const int wm = wid & 1, wn = wid >> 1;
    const int g = lane >> 2, tig = lane & 3;
    const int bM = blockIdx.y * 128, bN = blockIdx.x * 128;

    // loaders: 2 threads/row, 4x16B chunks each (row = 128 B)
    const int lrow = tid >> 1;
    const int lc0 = (tid & 1) << 2;
    const __half* Ag = A + (size_t)(bM + lrow) * lda;
    int wr = bN + lrow; if (wr >= N) wr = N - 1;
    const __half* Wg = W + (size_t)wr * ldw;

    const uint32_t sA = (uint32_t)__cvta_generic_to_shared(smh);
    const uint32_t sB = sA + 2 * BUFB;
    const uint32_t dRow = (uint32_t)lrow * (SROWH * 2);

    const uint32_t aoff = (uint32_t)((wm * 64 + (lane & 15)) * (SROWH * 2) + ((lane >> 4) << 4));
    const uint32_t boff = (uint32_t)((wn * 32 + ((lane >> 4) << 3) + (lane & 7)) * (SROWH * 2)
                                     + (((lane >> 3) & 1) << 4));

    float acc[4][4][4];
    #pragma unroll
    for (int i = 0; i < 4; i++)
        #pragma unroll
        for (int j = 0; j < 4; j++)
            #pragma unroll
            for (int q = 0; q < 4; q++) acc[i][j][q] = 0.f;

    const int KT = K / 64;
    #pragma unroll
    for (int c = 0; c < 4; c++) {
        cpasync16(sA + dRow + (lc0 + c) * 16, Ag + (lc0 + c) * 8);
        cpasync16(sB + dRow + (lc0 + c) * 16, Wg + (lc0 + c) * 8);
    }
    asm volatile("cp.async.commit_group;");

    for (int kt = 0; kt < KT; kt++) {
        const int buf = kt & 1;
        if (kt + 1 < KT) {
            const int nb = buf ^ 1;
            const int k2 = (kt + 1) * 64;
            #pragma unroll
            for (int c = 0; c < 4; c++) {
                cpasync16(sA + nb * BUFB + dRow + (lc0 + c) * 16, Ag + k2 + (lc0 + c) * 8);
                cpasync16(sB + nb * BUFB + dRow + (lc0 + c) * 16, Wg + k2 + (lc0 + c) * 8);
            }
            asm volatile("cp.async.commit_group;");
            asm volatile("cp.async.wait_group 1;");
        } else {
            asm volatile("cp.async.wait_group 0;");
        }
        __syncthreads();

        const uint32_t ab = sA + buf * BUFB;
        const uint32_t bb = sB + buf * BUFB;
        #pragma unroll
        for (int ks = 0; ks < 4; ks++) {
            uint32_t af[4][4], bf[4][2];
            #pragma unroll
            for (int i = 0; i < 4; i++)
                LDSM4(af[i][0], af[i][1], af[i][2], af[i][3],
                      ab + aoff + (uint32_t)(i * 16 * SROWH * 2 + ks * 32));
            #pragma unroll
            for (int jp = 0; jp < 2; jp++)
                LDSM4(bf[2*jp][0], bf[2*jp][1], bf[2*jp+1][0], bf[2*jp+1][1],
                      bb + boff + (uint32_t)(jp * 16 * SROWH * 2 + ks * 32));
            #pragma unroll
            for (int i = 0; i < 4; i++)
                #pragma unroll
                for (int j = 0; j < 4; j++)
                    mma_f16(acc[i][j], af[i][0], af[i][1], af[i][2], af[i][3],
                            bf[j][0], bf[j][1]);
        }
        __syncthreads();
    }

    // epilogue
    #pragma unroll
    for (int i = 0; i < 4; i++) {
        const int r0 = bM + wm * 64 + i * 16 + g;
        #pragma unroll
        for (int j = 0; j < 4; j++) {
            const int cn = bN + wn * 32 + j * 8 + tig * 2;
            #pragma unroll
            for (int q = 0; q < 4; q++) {
                const int r = r0 + (q >> 1) * 8;
                const int c = cn + (q & 1);
                if (c >= N) continue;
                float v = acc[i][j][q];
                if (epi == 0) { Cf[(size_t)r * ldc + c] = v; }
                else if (epi == 2) {
                    float u = v + bias[c];
                    Ch[(size_t)r * ldc + c] =
                        __float2half_rn(0.5f * u * (1.0f + erff(u * 0.70710678118654752f)));
                } else if (epi == 3) { Cf[(size_t)r * ldc + c] += v; }
                else if (epi == 5) {
                    float u = v + bias[c];
                    Ch[(size_t)r * ldc + c] =
                        __float2half_rn((u > 20.f) ? u : log1pf(expf(u)));
                } else if (epi == 6) { Ch[(size_t)r * ldc + c] = __float2half_rn(v); }
                else { // 7: residual + bias + mask (+copy)
                    int t = r & (TSEQ - 1), bidx = r >> 11;
                    float o = Cf[(size_t)r * ldc + c] + v + bias[c];
                    o = (t < lenp[bidx]) ? o : 0.f;
                    Cf[(size_t)r * ldc + c] = o;
                    if (out2) out2[(size_t)r * ldc + c] = o;
                }
            }
        }
    }
}

// ---------------- causal depthwise conv (k=4) + silu -------------------------
__global__ void k_conv(const __half* __restrict__ xz, const float* __restrict__ cw,
                       const float* __restrict__ cb, __half* __restrict__ xc) {
    int idx = blockIdx.x * 256 + threadIdx.x;
    int d = idx & (DI - 1);
    int m = idx >> 11;
    int t = m & (TSEQ - 1);
    float acc = cb[d];
    #pragma unroll
    for (int k = 0; k < 4; k++) {
        int tt = t + k - 3;
        if (tt >= 0)
            acc += __half2float(xz[(size_t)(m + k - 3) * (2 * DI) + d]) * cw[d * 4 + k];
    }
    float sg = 1.0f / (1.0f + expf(-acc));
    xc[idx] = __float2half_rn(acc * sg);
}

// ---------------- scan pass A -------------------------------------------------
__global__ __launch_bounds__(256) void k_scanA(
    const __half* __restrict__ dt, const __half* __restrict__ xc,
    const __half* __restrict__ xd, const float* __restrict__ Alog,
    float* __restrict__ gP, float* __restrict__ gS) {
    __shared__ float shB[CL][DS_];
    int b = blockIdx.z, c = blockIdx.y;
    int d = blockIdx.x * 256 + threadIdx.x;
    int mbase = b * TSEQ + c * CL;
    for (int idx = threadIdx.x; idx < CL * DS_; idx += 256) {
        int t = idx >> 4, col = idx & 15;
        shB[t][col] = __half2float(xd[(size_t)(mbase + t) * 96 + 64 + col]);
    }
    __syncthreads();
    float r[DS_];
    bool fast = true;
    #pragma unroll
    for (int n = 0; n < DS_; n++) {
        r[n] = expf(Alog[(size_t)d * DS_ + n]);
        fast = fast && (fabsf(r[n] - (float)(n + 1)) < 1e-3f * (float)(n + 1));
    }
    float P[DS_], S[DS_];
    #pragma unroll
    for (int n = 0; n < DS_; n++) { P[n] = 1.f; S[n] = 0.f; }
    for (int t = 0; t < CL; t++) {
        int m = mbase + t;
        float dv = __half2float(dt[(size_t)m * DI + d]);
        float xv = __half2float(xc[(size_t)m * DI + d]);
        float u = xv * dv;
        float dA[DS_];
        if (fast) {
            float e = expf(-dv);
            float p = 1.f;
            #pragma unroll
            for (int n = 0; n < DS_; n++) { p *= e; dA[n] = p; }
        } else {
            #pragma unroll
            for (int n = 0; n < DS_; n++) dA[n] = expf(-dv * r[n]);
        }
        #pragma unroll
        for (int n = 0; n < DS_; n++) {
            S[n] = S[n] * dA[n] + u * shB[t][n];
            P[n] *= dA[n];
        }
    }
    size_t base = (((size_t)b * NC + c) * DI + d) * DS_;
    #pragma unroll
    for (int n = 0; n < DS_; n += 4) {
        *(float4*)(gP + base + n) = make_float4(P[n], P[n+1], P[n+2], P[n+3]);
        *(float4*)(gS + base + n) = make_float4(S[n], S[n+1], S[n+2], S[n+3]);
    }
}

// ---------------- scan pass B -------------------------------------------------
__global__ void k_scanB(const float* __restrict__ gP, const float* __restrict__ gS,
                        float* __restrict__ gI) {
    int idx = blockIdx.x * 256 + threadIdx.x;
    int b = idx >> 11, d = idx & (DI - 1);
    float s[DS_];
    #pragma unroll
    for (int n = 0; n < DS_; n++) s[n] = 0.f;
    for (int c = 0; c < NC; c++) {
        size_t base = (((size_t)b * NC + c) * DI + d) * DS_;
        #pragma unroll
        for (int n = 0; n < DS_; n += 4)
            *(float4*)(gI + base + n) = make_float4(s[n], s[n+1], s[n+2], s[n+3]);
        #pragma unroll
        for (int n = 0; n < DS_; n += 4) {
            float4 P = *(const float4*)(gP + base + n);
            float4 S = *(const float4*)(gS + base + n);
            s[n+0] = s[n+0] * P.x + S.x;
            s[n+1] = s[n+1] * P.y + S.y;
            s[n+2] = s[n+2] * P.z + S.z;
            s[n+3] = s[n+3] * P.w + S.w;
        }
    }
}

// ---------------- scan pass C -------------------------------------------------
__global__ __launch_bounds__(256) void k_scanC(
    const __half* __restrict__ dt, const __half* __restrict__ xc,
    const __half* __restrict__ xd, const __half* __restrict__ xz,
    const float* __restrict__ Alog, const float* __restrict__ Dsk,
    const float* __restrict__ gI, __half* __restrict__ ym) {
    __shared__ float shB[CL][DS_];
    __shared__ float shC[CL][DS_];
    int b = blockIdx.z, c = blockIdx.y;
    int d = blockIdx.x * 256 + threadIdx.x;
    int mbase = b * TSEQ + c * CL;
    for (int idx = threadIdx.x; idx < CL * 32; idx += 256) {
        int t = idx >> 5, col = idx & 31;
        float v = __half2float(xd[(size_t)(mbase + t) * 96 + 64 + col]);
        if (col < 16) shB[t][col] = v;
        else shC[t][col - 16] = v;
    }
    __syncthreads();
    float r[DS_];
    bool fast = true;
    #pragma unroll
    for (int n = 0; n < DS_; n++) {
        r[n] = expf(Alog[(size_t)d * DS_ + n]);
        fast = fast && (fabsf(r[n] - (float)(n + 1)) < 1e-3f * (float)(n + 1));
    }
    float dskip = Dsk[d];
    float s[DS_];
    size_t base = (((size_t)b * NC + c) * DI + d) * DS_;
    #pragma unroll
    for (int n = 0; n < DS_; n += 4) {
        float4 v = *(const float4*)(gI + base + n);
        s[n+0] = v.x; s[n+1] = v.y; s[n+2] = v.z; s[n+3] = v.w;
    }
    for (int t = 0; t < CL; t++) {
        int m = mbase + t;
        float dv = __half2float(dt[(size_t)m * DI + d]);
        float xv = __half2float(xc[(size_t)m * DI + d]);
        float u = xv * dv;
        float dA[DS_];
        if (fast) {
            float e = expf(-dv);
            float p = 1.f;
            #pragma unroll
            for (int n = 0; n < DS_; n++) { p *= e; dA[n] = p; }
        } else {
            #pragma unroll
            for (int n = 0; n < DS_; n++) dA[n] = expf(-dv * r[n]);
        }
        float y = 0.f;
        #pragma unroll
        for (int n = 0; n < DS_; n++) {
            s[n] = s[n] * dA[n] + u * shB[t][n];
            y += s[n] * shC[t][n];
        }
        float z = __half2float(xz[(size_t)m * (2 * DI) + DI + d]);
        float sg = 1.0f / (1.0f + expf(-z));
        ym[(size_t)m * DI + d] = __float2half_rn((y + dskip * xv) * (z * sg));
    }
}

// ---------------- host orchestration -------------------------------------------
static void launch_gemm(const __half* A, const __half* W,
                        float* Cf, __half* Ch, const float* bias,
                        const int* lenp, float* out2,
                        int N, int K, int lda, int ldc, int epi) {
    dim3 grid((N + 127) / 128, MROWS / 128);
    k_gemm_tc<<<grid, 256, SMEM8>>>(A, W, Cf, Ch, bias, lenp, out2, N, K, lda, K, ldc, epi);
}

extern "C" void kernel_launch(void* const* d_in, const int* in_sizes, int n_in,
                              void* d_out, int out_size) {
    const float* x       = (const float*)d_in[0];
    const int*   lengths = (const int*)  d_in[1];
    const float* ln0_g   = (const float*)d_in[2];
    const float* ln0_b   = (const float*)d_in[3];
    const float* ln1_g   = (const float*)d_in[4];
    const float* ln1_b   = (const float*)d_in[5];
    const float* in_w    = (const float*)d_in[6];
    const float* conv_w  = (const float*)d_in[7];
    const float* conv_b  = (const float*)d_in[8];
    const float* xp_w    = (const float*)d_in[9];
    const float* dt_w    = (const float*)d_in[10];
    const float* dt_b    = (const float*)d_in[11];
    const float* A_log   = (const float*)d_in[12];
    const float* D_skip  = (const float*)d_in[13];
    const float* out_w   = (const float*)d_in[14];
    const float* ln2_g   = (const float*)d_in[15];
    const float* ln2_b   = (const float*)d_in[16];
    const float* f1_w    = (const float*)d_in[17];
    const float* f1_b    = (const float*)d_in[18];
    const float* f2_w    = (const float*)d_in[19];
    const float* f2_b    = (const float*)d_in[20];

    cudaFuncSetAttribute(k_gemm_tc, cudaFuncAttributeMaxDynamicSharedMemorySize, SMEM8);

    float *pX, *pP, *pS, *pI;
    __half *pXn, *pXz, *pXc, *pXd, *pDt, *pY, *pF, *pWa;
    cudaGetSymbolAddress((void**)&pX,  g_X);
    cudaGetSymbolAddress((void**)&pXn, g_Xn);
    cudaGetSymbolAddress((void**)&pXz, g_xz);
    cudaGetSymbolAddress((void**)&pXc, g_xc);
    cudaGetSymbolAddress((void**)&pXd, g_xd);
    cudaGetSymbolAddress((void**)&pDt, g_dt);
    cudaGetSymbolAddress((void**)&pY,  g_ym);
    cudaGetSymbolAddress((void**)&pF,  g_ffn);
    cudaGetSymbolAddress((void**)&pP,  g_cP);
    cudaGetSymbolAddress((void**)&pS,  g_cS);
    cudaGetSymbolAddress((void**)&pI,  g_cI);
    cudaGetSymbolAddress((void**)&pWa, g_wa);

    // convert ALL weights up front (contiguous across layers)
    k_round<<<(SZ_IN  / 4 + 255) / 256, 256>>>(in_w,  pWa + OW_IN,  SZ_IN  / 4);
    k_round<<<(SZ_XP  / 4 + 255) / 256, 256>>>(xp_w,  pWa + OW_XP,  SZ_XP  / 4);
    k_round<<<(SZ_DT  / 4 + 255) / 256, 256>>>(dt_w,  pWa + OW_DT,  SZ_DT  / 4);
    k_round<<<(SZ_OUT / 4 + 255) / 256, 256>>>(out_w, pWa + OW_OUT, SZ_OUT / 4);
    k_round<<<(SZ_F1  / 4 + 255) / 256, 256>>>(f1_w,  pWa + OW_F1,  SZ_F1  / 4);
    k_round<<<(SZ_F2  / 4 + 255) / 256, 256>>>(f2_w,  pWa + OW_F2,  SZ_F2  / 4);

    k_add_pe<<<(MROWS * DM) / 256, 256>>>(x, pX);
    k_ln<<<MROWS, 256>>>(pX, pX, ln0_g, ln0_b);

    for (int i = 0; i < 4; i++) {
        // --- Mamba block ---
        k_ln_h<<<MROWS, 256>>>(pX, pXn, ln1_g + i * DM, ln1_b + i * DM);
        launch_gemm(pXn, pWa + OW_IN + (size_t)i * 2 * DI * DM, nullptr, pXz, nullptr,
                    nullptr, nullptr, 2 * DI, DM, DM, 2 * DI, 6);
        k_conv<<<(MROWS * DI) / 256, 256>>>(pXz, conv_w + (size_t)i * DI * 4,
                                            conv_b + (size_t)i * DI, pXc);
        launch_gemm(pXc, pWa + OW_XP + (size_t)i * 96 * DI, nullptr, pXd, nullptr,
                    nullptr, nullptr, 96, DI, DI, 96, 6);
        launch_gemm(pXd, pWa + OW_DT + (size_t)i * DI * DTR, nullptr, pDt,
                    dt_b + (size_t)i * DI, nullptr, nullptr, DI, DTR, 96, DI, 5);
        dim3 sg(DI / 256, NC, BB);
        k_scanA<<<sg, 256>>>(pDt, pXc, pXd, A_log + (size_t)i * DI * DS_, pP, pS);
        k_scanB<<<(BB * DI) / 256, 256>>>(pP, pS, pI);
        k_scanC<<<sg, 256>>>(pDt, pXc, pXd, pXz, A_log + (size_t)i * DI * DS_,
                             D_skip + (size_t)i * DI, pI, pY);
        launch_gemm(pY, pWa + OW_OUT + (size_t)i * DM * DI, pX, nullptr, nullptr,
                    nullptr, nullptr, DM, DI, DI, DM, 3);
        // --- FFN block ---
        k_ln_h<<<MROWS, 256>>>(pX, pXn, ln2_g + i * DM, ln2_b + i * DM);
        launch_gemm(pXn, pWa + OW_F1 + (size_t)i * FFND * DM, nullptr, pF,
                    f1_b + (size_t)i * FFND, nullptr, nullptr, FFND, DM, DM, FFND, 2);
        launch_gemm(pF, pWa + OW_F2 + (size_t)i * DM * FFND, pX, nullptr,
                    f2_b + (size_t)i * DM, lengths,
                    (i == 3) ? (float*)d_out : nullptr, DM, FFND, FFND, DM, 7);
    }
}

// round 9
// speedup vs baseline: 1.9009x; 1.0156x over previous
#include <cuda_runtime.h>
#include <cuda_fp16.h>
#include <stdint.h>
#include <math.h>

#define BB    4
#define TSEQ  2048
#define DM    1024
#define DI    2048
#define DS_   16
#define DTR   64
#define FFND  3584
#define MROWS (BB*TSEQ)   // 8192
#define NC    32
#define CL    64

// ---------------- static device scratch -----------------------------------
__device__ float  g_X  [MROWS*DM];       // residual stream (fp32)
__device__ __half g_Xn [MROWS*DM];       // LN output
__device__ __half g_xz [MROWS*2*DI];     // in_proj output (half)
__device__ __half g_xc [MROWS*DI];       // conv+silu output
__device__ __half g_xd [MROWS*96];       // x_proj output (dt|B|C)
__device__ __half g_dt [MROWS*DI];       // softplus(dt) (half)
__device__ __half g_ym [MROWS*DI];       // gated scan output
__device__ __half g_ffn[MROWS*FFND];     // ffn hidden
__device__ float  g_cP [BB*NC*DI*DS_];
__device__ float  g_cS [BB*NC*DI*DS_];
__device__ float  g_cI [BB*NC*DI*DS_];
__device__ __half g_wa [56*1024*1024];   // all weights, f16

// weight scratch offsets (halves)
#define OW_IN   0
#define SZ_IN   (4*2*DI*DM)
#define OW_XP   (OW_IN + SZ_IN)
#define SZ_XP   (4*96*DI)
#define OW_DT   (OW_XP + SZ_XP)
#define SZ_DT   (4*DI*DTR)
#define OW_OUT  (OW_DT + SZ_DT)
#define SZ_OUT  (4*DM*DI)
#define OW_F1   (OW_OUT + SZ_OUT)
#define SZ_F1   (4*FFND*DM)
#define OW_F2   (OW_F1 + SZ_F1)
#define SZ_F2   (4*DM*FFND)

// ---------------- helpers ---------------------------------------------------
__device__ __forceinline__ void cpasync16(uint32_t dst, const void* src) {
    asm volatile("cp.async.ca.shared.global [%0], [%1], 16;" :: "r"(dst), "l"(src));
}
#define LDSM4(r0, r1, r2, r3, a) \
    asm volatile("ldmatrix.sync.aligned.m8n8.x4.shared.b16 {%0,%1,%2,%3}, [%4];" \
        : "=r"(r0), "=r"(r1), "=r"(r2), "=r"(r3) : "r"(a))
__device__ __forceinline__ void mma_f16(float c[4], uint32_t a0, uint32_t a1,
                                        uint32_t a2, uint32_t a3,
                                        uint32_t b0, uint32_t b1) {
    asm volatile(
        "mma.sync.aligned.m16n8k16.row.col.f32.f16.f16.f32 "
        "{%0,%1,%2,%3}, {%4,%5,%6,%7}, {%8,%9}, {%0,%1,%2,%3};"
        : "+f"(c[0]), "+f"(c[1]), "+f"(c[2]), "+f"(c[3])
        : "r"(a0), "r"(a1), "r"(a2), "r"(a3), "r"(b0), "r"(b1));
}

// ---------------- weight convert f32 -> f16 ---------------------------------
__global__ void k_round(const float* __restrict__ in, __half* __restrict__ out, int n4) {
    int i = blockIdx.x * 256 + threadIdx.x;
    if (i < n4) {
        float4 v = ((const float4*)in)[i];
        __half2 h0 = __floats2half2_rn(v.x, v.y);
        __half2 h1 = __floats2half2_rn(v.z, v.w);
        ((uint2*)out)[i] = make_uint2(*(uint32_t*)&h0, *(uint32_t*)&h1);
    }
}

// ---------------- positional encoding ---------------------------------------
__global__ void k_add_pe(const float* __restrict__ xin, float* __restrict__ X) {
    int idx = blockIdx.x * 256 + threadIdx.x;
    int d = idx & (DM - 1);
    int m = idx >> 10;
    int t = m & (TSEQ - 1);
    int p2 = d & ~1;
    float freq = expf((float)p2 * (-9.210340371976184f / (float)DM));
    float ang = (float)t * freq;
    float pe = (d & 1) ? cosf(ang) : sinf(ang);
    X[idx] = xin[idx] + pe;
}

// ---------------- layernorm --------------------------------------------------
__device__ __forceinline__ float blockReduce(float v, float* sh) {
    int lane = threadIdx.x & 31, wid = threadIdx.x >> 5;
    #pragma unroll
    for (int o = 16; o > 0; o >>= 1) v += __shfl_down_sync(0xffffffffu, v, o);
    if (lane == 0) sh[wid] = v;
    __syncthreads();
    if (threadIdx.x == 0) {
        float s = 0.f;
        #pragma unroll
        for (int i = 0; i < 8; i++) s += sh[i];
        sh[32] = s;
    }
    __syncthreads();
    float r = sh[32];
    __syncthreads();
    return r;
}

__global__ __launch_bounds__(256) void k_ln(const float* __restrict__ in,
                                            float* __restrict__ out,
                                            const float* __restrict__ g,
                                            const float* __restrict__ b) {
    __shared__ float sh[33];
    int row = blockIdx.x;
    float4 v = ((const float4*)(in + (size_t)row * DM))[threadIdx.x];
    float mean = blockReduce(v.x + v.y + v.z + v.w, sh) * (1.0f / DM);
    float dx = v.x - mean, dy = v.y - mean, dz = v.z - mean, dw = v.w - mean;
    float var = blockReduce(dx*dx + dy*dy + dz*dz + dw*dw, sh) * (1.0f / DM);
    float rstd = rsqrtf(var + 1e-5f);
    int c = threadIdx.x * 4;
    float4 o;
    o.x = dx * rstd * g[c + 0] + b[c + 0];
    o.y = dy * rstd * g[c + 1] + b[c + 1];
    o.z = dz * rstd * g[c + 2] + b[c + 2];
    o.w = dw * rstd * g[c + 3] + b[c + 3];
    ((float4*)(out + (size_t)row * DM))[threadIdx.x] = o;
}

__global__ __launch_bounds__(256) void k_ln_h(const float* __restrict__ in,
                                              __half* __restrict__ out,
                                              const float* __restrict__ g,
                                              const float* __restrict__ b) {
    __shared__ float sh[33];
    int row = blockIdx.x;
    float4 v = ((const float4*)(in + (size_t)row * DM))[threadIdx.x];
    float mean = blockReduce(v.x + v.y + v.z + v.w, sh) * (1.0f / DM);
    float dx = v.x - mean, dy = v.y - mean, dz = v.z - mean, dw = v.w - mean;
    float var = blockReduce(dx*dx + dy*dy + dz*dz + dw*dw, sh) * (1.0f / DM);
    float rstd = rsqrtf(var + 1e-5f);
    int c = threadIdx.x * 4;
    __half2 h0 = __floats2half2_rn(dx * rstd * g[c+0] + b[c+0], dy * rstd * g[c+1] + b[c+1]);
    __half2 h1 = __floats2half2_rn(dz * rstd * g[c+2] + b[c+2], dw * rstd * g[c+3] + b[c+3]);
    ((uint2*)(out + (size_t)row * DM))[threadIdx.x] = make_uint2(*(uint32_t*)&h0, *(uint32_t*)&h1);
}

// ---------------- fp16 tensor-core GEMM --------------------------------------
// C[m,n] = sum_k A[m,k]*W[n,k]; CTA 128x128, 8 warps (2x4), warp 64x32.
// 4-stage cp.async pipeline, BK=32, prefetch distance 2, 1 barrier/iter.
// epi: 0:Cf=v 2:Ch=gelu(v+b) 3:Cf+=v 5:Ch=softplus(v+b) 6:Ch=v
//      7:Cf=(Cf+v+b)*mask (+out2 copy)
#define SROWH 40                           // halves per smem row (80 B)
#define ABUF  (128 * SROWH * 2)            // 10240 B per stage per matrix
#define SMEM9 (8 * ABUF)                   // 81920 B (4 stages x A,B)

__global__ __launch_bounds__(256, 2) void k_gemm_tc(
    const __half* __restrict__ A, const __half* __restrict__ W,
    float* __restrict__ Cf, __half* __restrict__ Ch, const float* __restrict__ bias,
    const int* __restrict__ lenp, float* __restrict__ out2,
    int N, int K, int lda, int ldw, int ldc, int epi) {
    extern __shared__ __half smh[];
    const int tid = threadIdx.x;
    const int lane = tid & 31;
    const int wid = tid >> 5;
    const int wm = wid & 1, wn = wid >> 1;
    const int g = lane >> 2, tig = lane & 3;
    const int bM = blockIdx.y * 128, bN = blockIdx.x * 128;

    // loaders: 2 threads/row, 2x16B chunks each (row = 64 B)
    const int lrow = tid >> 1;
    const int lc0 = (tid & 1) << 1;
    const __half* Ag = A + (size_t)(bM + lrow) * lda;
    int wr = bN + lrow; if (wr >= N) wr = N - 1;
    const __half* Wg = W + (size_t)wr * ldw;

    const uint32_t sA = (uint32_t)__cvta_generic_to_shared(smh);
    const uint32_t sB = sA + 4 * ABUF;
    const uint32_t dRow = (uint32_t)lrow * (SROWH * 2);

    const uint32_t aoff = (uint32_t)((wm * 64 + (lane & 15)) * (SROWH * 2) + ((lane >> 4) << 4));
    const uint32_t boff = (uint32_t)((wn * 32 + ((lane >> 4) << 3) + (lane & 7)) * (SROWH * 2)
                                     + (((lane >> 3) & 1) << 4));

    float acc[4][4][4];
    #pragma unroll
    for (int i = 0; i < 4; i++)
        #pragma unroll
        for (int j = 0; j < 4; j++)
            #pragma unroll
            for (int q = 0; q < 4; q++) acc[i][j][q] = 0.f;

    const int KT = K / 32;

    // prologue: tiles 0,1 -> stages 0,1
    #pragma unroll
    for (int s = 0; s < 2; s++) {
        const int k2 = s * 32;
        #pragma unroll
        for (int c = 0; c < 2; c++) {
            cpasync16(sA + s * ABUF + dRow + (lc0 + c) * 16, Ag + k2 + (lc0 + c) * 8);
            cpasync16(sB + s * ABUF + dRow + (lc0 + c) * 16, Wg + k2 + (lc0 + c) * 8);
        }
        asm volatile("cp.async.commit_group;");
    }

    for (int j = 0; j < KT; j++) {
        if (j + 2 < KT) {
            const int stg = (j + 2) & 3;
            const int k2 = (j + 2) * 32;
            #pragma unroll
            for (int c = 0; c < 2; c++) {
                cpasync16(sA + stg * ABUF + dRow + (lc0 + c) * 16, Ag + k2 + (lc0 + c) * 8);
                cpasync16(sB + stg * ABUF + dRow + (lc0 + c) * 16, Wg + k2 + (lc0 + c) * 8);
            }
            asm volatile("cp.async.commit_group;");
            asm volatile("cp.async.wait_group 2;");
        } else if (j + 1 < KT) {
            asm volatile("cp.async.wait_group 1;");
        } else {
            asm volatile("cp.async.wait_group 0;");
        }
        __syncthreads();

        const int buf = j & 3;
        const uint32_t ab = sA + buf * ABUF;
        const uint32_t bb = sB + buf * ABUF;
        #pragma unroll
        for (int ks = 0; ks < 2; ks++) {
            uint32_t af[4][4], bf[4][2];
            #pragma unroll
            for (int i = 0; i < 4; i++)
                LDSM4(af[i][0], af[i][1], af[i][2], af[i][3],
                      ab + aoff + (uint32_t)(i * 16 * SROWH * 2 + ks * 32));
            #pragma unroll
            for (int jp = 0; jp < 2; jp++)
                LDSM4(bf[2*jp][0], bf[2*jp][1], bf[2*jp+1][0], bf[2*jp+1][1],
                      bb + boff + (uint32_t)(jp * 16 * SROWH * 2 + ks * 32));
            #pragma unroll
            for (int i = 0; i < 4; i++)
                #pragma unroll
                for (int jj = 0; jj < 4; jj++)
                    mma_f16(acc[i][jj], af[i][0], af[i][1], af[i][2], af[i][3],
                            bf[jj][0], bf[jj][1]);
        }
    }

    // epilogue
    #pragma unroll
    for (int i = 0; i < 4; i++) {
        const int r0 = bM + wm * 64 + i * 16 + g;
        #pragma unroll
        for (int j = 0; j < 4; j++) {
            const int cn = bN + wn * 32 + j * 8 + tig * 2;
            #pragma unroll
            for (int q = 0; q < 4; q++) {
                const int r = r0 + (q >> 1) * 8;
                const int c = cn + (q & 1);
                if (c >= N) continue;
                float v = acc[i][j][q];
                if (epi == 0) { Cf[(size_t)r * ldc + c] = v; }
                else if (epi == 2) {
                    float u = v + bias[c];
                    Ch[(size_t)r * ldc + c] =
                        __float2half_rn(0.5f * u * (1.0f + erff(u * 0.70710678118654752f)));
                } else if (epi == 3) { Cf[(size_t)r * ldc + c] += v; }
                else if (epi == 5) {
                    float u = v + bias[c];
                    Ch[(size_t)r * ldc + c] =
                        __float2half_rn((u > 20.f) ? u : log1pf(expf(u)));
                } else if (epi == 6) { Ch[(size_t)r * ldc + c] = __float2half_rn(v); }
                else {
                    int t = r & (TSEQ - 1), bidx = r >> 11;
                    float o = Cf[(size_t)r * ldc + c] + v + bias[c];
                    o = (t < lenp[bidx]) ? o : 0.f;
                    Cf[(size_t)r * ldc + c] = o;
                    if (out2) out2[(size_t)r * ldc + c] = o;
                }
            }
        }
    }
}

// ---------------- causal depthwise conv (k=4) + silu -------------------------
__global__ void k_conv(const __half* __restrict__ xz, const float* __restrict__ cw,
                       const float* __restrict__ cb, __half* __restrict__ xc) {
    int idx = blockIdx.x * 256 + threadIdx.x;
    int d = idx & (DI - 1);
    int m = idx >> 11;
    int t = m & (TSEQ - 1);
    float acc = cb[d];
    #pragma unroll
    for (int k = 0; k < 4; k++) {
        int tt = t + k - 3;
        if (tt >= 0)
            acc += __half2float(xz[(size_t)(m + k - 3) * (2 * DI) + d]) * cw[d * 4 + k];
    }
    float sg = 1.0f / (1.0f + expf(-acc));
    xc[idx] = __float2half_rn(acc * sg);
}

// ---------------- scan pass A -------------------------------------------------
__global__ __launch_bounds__(256) void k_scanA(
    const __half* __restrict__ dt, const __half* __restrict__ xc,
    const __half* __restrict__ xd, const float* __restrict__ Alog,
    float* __restrict__ gP, float* __restrict__ gS) {
    __shared__ float shB[CL][DS_];
    int b = blockIdx.z, c = blockIdx.y;
    int d = blockIdx.x * 256 + threadIdx.x;
    int mbase = b * TSEQ + c * CL;
    for (int idx = threadIdx.x; idx < CL * DS_; idx += 256) {
        int t = idx >> 4, col = idx & 15;
        shB[t][col] = __half2float(xd[(size_t)(mbase + t) * 96 + 64 + col]);
    }
    __syncthreads();
    float r[DS_];
    bool fast = true;
    #pragma unroll
    for (int n = 0; n < DS_; n++) {
        r[n] = expf(Alog[(size_t)d * DS_ + n]);
        fast = fast && (fabsf(r[n] - (float)(n + 1)) < 1e-3f * (float)(n + 1));
    }
    float P[DS_], S[DS_];
    #pragma unroll
    for (int n = 0; n < DS_; n++) { P[n] = 1.f; S[n] = 0.f; }
    for (int t = 0; t < CL; t++) {
        int m = mbase + t;
        float dv = __half2float(dt[(size_t)m * DI + d]);
        float xv = __half2float(xc[(size_t)m * DI + d]);
        float u = xv * dv;
        float dA[DS_];
        if (fast) {
            float e = expf(-dv);
            float p = 1.f;
            #pragma unroll
            for (int n = 0; n < DS_; n++) { p *= e; dA[n] = p; }
        } else {
            #pragma unroll
            for (int n = 0; n < DS_; n++) dA[n] = expf(-dv * r[n]);
        }
        #pragma unroll
        for (int n = 0; n < DS_; n++) {
            S[n] = S[n] * dA[n] + u * shB[t][n];
            P[n] *= dA[n];
        }
    }
    size_t base = (((size_t)b * NC + c) * DI + d) * DS_;
    #pragma unroll
    for (int n = 0; n < DS_; n += 4) {
        *(float4*)(gP + base + n) = make_float4(P[n], P[n+1], P[n+2], P[n+3]);
        *(float4*)(gS + base + n) = make_float4(S[n], S[n+1], S[n+2], S[n+3]);
    }
}

// ---------------- scan pass B -------------------------------------------------
__global__ void k_scanB(const float* __restrict__ gP, const float* __restrict__ gS,
                        float* __restrict__ gI) {
    int idx = blockIdx.x * 256 + threadIdx.x;
    int b = idx >> 11, d = idx & (DI - 1);
    float s[DS_];
    #pragma unroll
    for (int n = 0; n < DS_; n++) s[n] = 0.f;
    for (int c = 0; c < NC; c++) {
        size_t base = (((size_t)b * NC + c) * DI + d) * DS_;
        #pragma unroll
        for (int n = 0; n < DS_; n += 4)
            *(float4*)(gI + base + n) = make_float4(s[n], s[n+1], s[n+2], s[n+3]);
        #pragma unroll
        for (int n = 0; n < DS_; n += 4) {
            float4 P = *(const float4*)(gP + base + n);
            float4 S = *(const float4*)(gS + base + n);
            s[n+0] = s[n+0] * P.x + S.x;
            s[n+1] = s[n+1] * P.y + S.y;
            s[n+2] = s[n+2] * P.z + S.z;
            s[n+3] = s[n+3] * P.w + S.w;
        }
    }
}

// ---------------- scan pass C -------------------------------------------------
__global__ __launch_bounds__(256) void k_scanC(
    const __half* __restrict__ dt, const __half* __restrict__ xc,
    const __half* __restrict__ xd, const __half* __restrict__ xz,
    const float* __restrict__ Alog, const float* __restrict__ Dsk,
    const float* __restrict__ gI, __half* __restrict__ ym) {
    __shared__ float shB[CL][DS_];
    __shared__ float shC[CL][DS_];
    int b = blockIdx.z, c = blockIdx.y;
    int d = blockIdx.x * 256 + threadIdx.x;
    int mbase = b * TSEQ + c * CL;
    for (int idx = threadIdx.x; idx < CL * 32; idx += 256) {
        int t = idx >> 5, col = idx & 31;
        float v = __half2float(xd[(size_t)(mbase + t) * 96 + 64 + col]);
        if (col < 16) shB[t][col] = v;
        else shC[t][col - 16] = v;
    }
    __syncthreads();
    float r[DS_];
    bool fast = true;
    #pragma unroll
    for (int n = 0; n < DS_; n++) {
        r[n] = expf(Alog[(size_t)d * DS_ + n]);
        fast = fast && (fabsf(r[n] - (float)(n + 1)) < 1e-3f * (float)(n + 1));
    }
    float dskip = Dsk[d];
    float s[DS_];
    size_t base = (((size_t)b * NC + c) * DI + d) * DS_;
    #pragma unroll
    for (int n = 0; n < DS_; n += 4) {
        float4 v = *(const float4*)(gI + base + n);
        s[n+0] = v.x; s[n+1] = v.y; s[n+2] = v.z; s[n+3] = v.w;
    }
    for (int t = 0; t < CL; t++) {
        int m = mbase + t;
        float dv = __half2float(dt[(size_t)m * DI + d]);
        float xv = __half2float(xc[(size_t)m * DI + d]);
        float u = xv * dv;
        float dA[DS_];
        if (fast) {
            float e = expf(-dv);
            float p = 1.f;
            #pragma unroll
            for (int n = 0; n < DS_; n++) { p *= e; dA[n] = p; }
        } else {
            #pragma unroll
            for (int n = 0; n < DS_; n++) dA[n] = expf(-dv * r[n]);
        }
        float y = 0.f;
        #pragma unroll
        for (int n = 0; n < DS_; n++) {
            s[n] = s[n] * dA[n] + u * shB[t][n];
            y += s[n] * shC[t][n];
        }
        float z = __half2float(xz[(size_t)m * (2 * DI) + DI + d]);
        float sg = 1.0f / (1.0f + expf(-z));
        ym[(size_t)m * DI + d] = __float2half_rn((y + dskip * xv) * (z * sg));
    }
}

// ---------------- host orchestration -------------------------------------------
static void launch_gemm(const __half* A, const __half* W,
                        float* Cf, __half* Ch, const float* bias,
                        const int* lenp, float* out2,
                        int N, int K, int lda, int ldc, int epi) {
    dim3 grid((N + 127) / 128, MROWS / 128);
    k_gemm_tc<<<grid, 256, SMEM9>>>(A, W, Cf, Ch, bias, lenp, out2, N, K, lda, K, ldc, epi);
}

extern "C" void kernel_launch(void* const* d_in, const int* in_sizes, int n_in,
                              void* d_out, int out_size) {
    const float* x       = (const float*)d_in[0];
    const int*   lengths = (const int*)  d_in[1];
    const float* ln0_g   = (const float*)d_in[2];
    const float* ln0_b   = (const float*)d_in[3];
    const float* ln1_g   = (const float*)d_in[4];
    const float* ln1_b   = (const float*)d_in[5];
    const float* in_w    = (const float*)d_in[6];
    const float* conv_w  = (const float*)d_in[7];
    const float* conv_b  = (const float*)d_in[8];
    const float* xp_w    = (const float*)d_in[9];
    const float* dt_w    = (const float*)d_in[10];
    const float* dt_b    = (const float*)d_in[11];
    const float* A_log   = (const float*)d_in[12];
    const float* D_skip  = (const float*)d_in[13];
    const float* out_w   = (const float*)d_in[14];
    const float* ln2_g   = (const float*)d_in[15];
    const float* ln2_b   = (const float*)d_in[16];
    const float* f1_w    = (const float*)d_in[17];
    const float* f1_b    = (const float*)d_in[18];
    const float* f2_w    = (const float*)d_in[19];
    const float* f2_b    = (const float*)d_in[20];

    cudaFuncSetAttribute(k_gemm_tc, cudaFuncAttributeMaxDynamicSharedMemorySize, SMEM9);

    float *pX, *pP, *pS, *pI;
    __half *pXn, *pXz, *pXc, *pXd, *pDt, *pY, *pF, *pWa;
    cudaGetSymbolAddress((void**)&pX,  g_X);
    cudaGetSymbolAddress((void**)&pXn, g_Xn);
    cudaGetSymbolAddress((void**)&pXz, g_xz);
    cudaGetSymbolAddress((void**)&pXc, g_xc);
    cudaGetSymbolAddress((void**)&pXd, g_xd);
    cudaGetSymbolAddress((void**)&pDt, g_dt);
    cudaGetSymbolAddress((void**)&pY,  g_ym);
    cudaGetSymbolAddress((void**)&pF,  g_ffn);
    cudaGetSymbolAddress((void**)&pP,  g_cP);
    cudaGetSymbolAddress((void**)&pS,  g_cS);
    cudaGetSymbolAddress((void**)&pI,  g_cI);
    cudaGetSymbolAddress((void**)&pWa, g_wa);

    // convert ALL weights up front
    k_round<<<(SZ_IN  / 4 + 255) / 256, 256>>>(in_w,  pWa + OW_IN,  SZ_IN  / 4);
    k_round<<<(SZ_XP  / 4 + 255) / 256, 256>>>(xp_w,  pWa + OW_XP,  SZ_XP  / 4);
    k_round<<<(SZ_DT  / 4 + 255) / 256, 256>>>(dt_w,  pWa + OW_DT,  SZ_DT  / 4);
    k_round<<<(SZ_OUT / 4 + 255) / 256, 256>>>(out_w, pWa + OW_OUT, SZ_OUT / 4);
    k_round<<<(SZ_F1  / 4 + 255) / 256, 256>>>(f1_w,  pWa + OW_F1,  SZ_F1  / 4);
    k_round<<<(SZ_F2  / 4 + 255) / 256, 256>>>(f2_w,  pWa + OW_F2,  SZ_F2  / 4);

    k_add_pe<<<(MROWS * DM) / 256, 256>>>(x, pX);
    k_ln<<<MROWS, 256>>>(pX, pX, ln0_g, ln0_b);

    for (int i = 0; i < 4; i++) {
        // --- Mamba block ---
        k_ln_h<<<MROWS, 256>>>(pX, pXn, ln1_g + i * DM, ln1_b + i * DM);
        launch_gemm(pXn, pWa + OW_IN + (size_t)i * 2 * DI * DM, nullptr, pXz, nullptr,
                    nullptr, nullptr, 2 * DI, DM, DM, 2 * DI, 6);
        k_conv<<<(MROWS * DI) / 256, 256>>>(pXz, conv_w + (size_t)i * DI * 4,
                                            conv_b + (size_t)i * DI, pXc);
        launch_gemm(pXc, pWa + OW_XP + (size_t)i * 96 * DI, nullptr, pXd, nullptr,
                    nullptr, nullptr, 96, DI, DI, 96, 6);
        launch_gemm(pXd, pWa + OW_DT + (size_t)i * DI * DTR, nullptr, pDt,
                    dt_b + (size_t)i * DI, nullptr, nullptr, DI, DTR, 96, DI, 5);
        dim3 sg(DI / 256, NC, BB);
        k_scanA<<<sg, 256>>>(pDt, pXc, pXd, A_log + (size_t)i * DI * DS_, pP, pS);
        k_scanB<<<(BB * DI) / 256, 256>>>(pP, pS, pI);
        k_scanC<<<sg, 256>>>(pDt, pXc, pXd, pXz, A_log + (size_t)i * DI * DS_,
                             D_skip + (size_t)i * DI, pI, pY);
        launch_gemm(pY, pWa + OW_OUT + (size_t)i * DM * DI, pX, nullptr, nullptr,
                    nullptr, nullptr, DM, DI, DI, DM, 3);
        // --- FFN block ---
        k_ln_h<<<MROWS, 256>>>(pX, pXn, ln2_g + i * DM, ln2_b + i * DM);
        launch_gemm(pXn, pWa + OW_F1 + (size_t)i * FFND * DM, nullptr, pF,
                    f1_b + (size_t)i * FFND, nullptr, nullptr, FFND, DM, DM, FFND, 2);
        launch_gemm(pF, pWa + OW_F2 + (size_t)i * DM * FFND, pX, nullptr,
                    f2_b + (size_t)i * DM, lengths,
                    (i == 3) ? (float*)d_out : nullptr, DM, FFND, FFND, DM, 7);
    }
}

// round 10
// speedup vs baseline: 1.9611x; 1.0317x over previous
#include <cuda_runtime.h>
#include <cuda_fp16.h>
#include <stdint.h>
#include <math.h>

#define BB    4
#define TSEQ  2048
#define DM    1024
#define DI    2048
#define DS_   16
#define DTR   64
#define FFND  3584
#define MROWS (BB*TSEQ)   // 8192
#define NC    32
#define CL    64

// ---------------- static device scratch -----------------------------------
__device__ float  g_X  [MROWS*DM];       // residual stream (fp32)
__device__ __half g_Xn [MROWS*DM];       // LN output
__device__ __half g_xz [MROWS*2*DI];     // in_proj output (half)
__device__ __half g_xc [MROWS*DI];       // conv+silu output
__device__ __half g_xd [MROWS*96];       // x_proj output (dt|B|C)
__device__ __half g_dt [MROWS*DI];       // softplus(dt) (half)
__device__ __half g_ym [MROWS*DI];       // gated scan output
__device__ __half g_ffn[MROWS*FFND];     // ffn hidden
__device__ float  g_cP [BB*NC*DI*DS_];
__device__ float  g_cS [BB*NC*DI*DS_];
__device__ float  g_cI [BB*NC*DI*DS_];
__device__ __half g_wa [56*1024*1024];   // all weights, f16

// weight scratch offsets (halves)
#define OW_IN   0
#define SZ_IN   (4*2*DI*DM)
#define OW_XP   (OW_IN + SZ_IN)
#define SZ_XP   (4*96*DI)
#define OW_DT   (OW_XP + SZ_XP)
#define SZ_DT   (4*DI*DTR)
#define OW_OUT  (OW_DT + SZ_DT)
#define SZ_OUT  (4*DM*DI)
#define OW_F1   (OW_OUT + SZ_OUT)
#define SZ_F1   (4*FFND*DM)
#define OW_F2   (OW_F1 + SZ_F1)
#define SZ_F2   (4*DM*FFND)

// ---------------- helpers ---------------------------------------------------
__device__ __forceinline__ void cpasync16(uint32_t dst, const void* src) {
    asm volatile("cp.async.cg.shared.global [%0], [%1], 16;" :: "r"(dst), "l"(src));
}
#define LDSM4(r0, r1, r2, r3, a) \
    asm volatile("ldmatrix.sync.aligned.m8n8.x4.shared.b16 {%0,%1,%2,%3}, [%4];" \
        : "=r"(r0), "=r"(r1), "=r"(r2), "=r"(r3) : "r"(a))
__device__ __forceinline__ void mma_f16(float c[4], uint32_t a0, uint32_t a1,
                                        uint32_t a2, uint32_t a3,
                                        uint32_t b0, uint32_t b1) {
    asm volatile(
        "mma.sync.aligned.m16n8k16.row.col.f32.f16.f16.f32 "
        "{%0,%1,%2,%3}, {%4,%5,%6,%7}, {%8,%9}, {%0,%1,%2,%3};"
        : "+f"(c[0]), "+f"(c[1]), "+f"(c[2]), "+f"(c[3])
        : "r"(a0), "r"(a1), "r"(a2), "r"(a3), "r"(b0), "r"(b1));
}
__device__ __forceinline__ uint2 cvt4(float4 v) {
    __half2 h0 = __floats2half2_rn(v.x, v.y);
    __half2 h1 = __floats2half2_rn(v.z, v.w);
    return make_uint2(*(uint32_t*)&h0, *(uint32_t*)&h1);
}

// ---------------- weight convert f32 -> f16 ---------------------------------
__global__ void k_round(const float* __restrict__ in, __half* __restrict__ out, int n4) {
    int i = blockIdx.x * 256 + threadIdx.x;
    if (i < n4) ((uint2*)out)[i] = cvt4(((const float4*)in)[i]);
}
// 5 packed segments
__global__ void k_round5(
    const float* __restrict__ a, __half* __restrict__ oa, int na,
    const float* __restrict__ b, __half* __restrict__ ob, int nb,
    const float* __restrict__ c, __half* __restrict__ oc, int ncnt,
    const float* __restrict__ d, __half* __restrict__ od, int nd,
    const float* __restrict__ e, __half* __restrict__ oe, int ne) {
    int i = blockIdx.x * 256 + threadIdx.x;
    const float* s; __half* o;
    if (i < na) { s = a; o = oa; }
    else { i -= na;
      if (i < nb) { s = b; o = ob; }
      else { i -= nb;
        if (i < ncnt) { s = c; o = oc; }
        else { i -= ncnt;
          if (i < nd) { s = d; o = od; }
          else { i -= nd; if (i >= ne) return; s = e; o = oe; } } } }
    ((uint2*)o)[i] = cvt4(((const float4*)s)[i]);
}

// ---------------- block reduce ----------------------------------------------
__device__ __forceinline__ float blockReduce(float v, float* sh) {
    int lane = threadIdx.x & 31, wid = threadIdx.x >> 5;
    #pragma unroll
    for (int o = 16; o > 0; o >>= 1) v += __shfl_down_sync(0xffffffffu, v, o);
    if (lane == 0) sh[wid] = v;
    __syncthreads();
    if (threadIdx.x == 0) {
        float s = 0.f;
        #pragma unroll
        for (int i = 0; i < 8; i++) s += sh[i];
        sh[32] = s;
    }
    __syncthreads();
    float r = sh[32];
    __syncthreads();
    return r;
}

// ---------------- fused PE + ln0 + ln1(->half) --------------------------------
__global__ __launch_bounds__(256) void k_peln2(
    const float* __restrict__ xin, float* __restrict__ X, __half* __restrict__ Xn,
    const float* __restrict__ g0, const float* __restrict__ b0,
    const float* __restrict__ g1, const float* __restrict__ b1) {
    __shared__ float sh[33];
    int row = blockIdx.x;
    int t = row & (TSEQ - 1);
    int c = threadIdx.x * 4;
    float4 v = ((const float4*)(xin + (size_t)row * DM))[threadIdx.x];
    float pv[4];
    #pragma unroll
    for (int j = 0; j < 4; j++) {
        int d = c + j;
        float freq = expf((float)(d & ~1) * (-9.210340371976184f / (float)DM));
        float ang = (float)t * freq;
        pv[j] = (d & 1) ? cosf(ang) : sinf(ang);
    }
    v.x += pv[0]; v.y += pv[1]; v.z += pv[2]; v.w += pv[3];
    float mean = blockReduce(v.x + v.y + v.z + v.w, sh) * (1.0f / DM);
    float dx = v.x - mean, dy = v.y - mean, dz = v.z - mean, dw = v.w - mean;
    float var = blockReduce(dx*dx + dy*dy + dz*dz + dw*dw, sh) * (1.0f / DM);
    float rstd = rsqrtf(var + 1e-5f);
    float4 o;
    o.x = dx * rstd * g0[c + 0] + b0[c + 0];
    o.y = dy * rstd * g0[c + 1] + b0[c + 1];
    o.z = dz * rstd * g0[c + 2] + b0[c + 2];
    o.w = dw * rstd * g0[c + 3] + b0[c + 3];
    ((float4*)(X + (size_t)row * DM))[threadIdx.x] = o;
    // second LN on o
    float m2 = blockReduce(o.x + o.y + o.z + o.w, sh) * (1.0f / DM);
    float ex = o.x - m2, ey = o.y - m2, ez = o.z - m2, ew = o.w - m2;
    float v2 = blockReduce(ex*ex + ey*ey + ez*ez + ew*ew, sh) * (1.0f / DM);
    float r2 = rsqrtf(v2 + 1e-5f);
    float4 q;
    q.x = ex * r2 * g1[c + 0] + b1[c + 0];
    q.y = ey * r2 * g1[c + 1] + b1[c + 1];
    q.z = ez * r2 * g1[c + 2] + b1[c + 2];
    q.w = ew * r2 * g1[c + 3] + b1[c + 3];
    ((uint2*)(Xn + (size_t)row * DM))[threadIdx.x] = cvt4(q);
}

// ---------------- layernorm (fp32 in, half out) --------------------------------
__global__ __launch_bounds__(256) void k_ln_h(const float* __restrict__ in,
                                              __half* __restrict__ out,
                                              const float* __restrict__ g,
                                              const float* __restrict__ b) {
    __shared__ float sh[33];
    int row = blockIdx.x;
    float4 v = ((const float4*)(in + (size_t)row * DM))[threadIdx.x];
    float mean = blockReduce(v.x + v.y + v.z + v.w, sh) * (1.0f / DM);
    float dx = v.x - mean, dy = v.y - mean, dz = v.z - mean, dw = v.w - mean;
    float var = blockReduce(dx*dx + dy*dy + dz*dz + dw*dw, sh) * (1.0f / DM);
    float rstd = rsqrtf(var + 1e-5f);
    int c = threadIdx.x * 4;
    float4 q;
    q.x = dx * rstd * g[c + 0] + b[c + 0];
    q.y = dy * rstd * g[c + 1] + b[c + 1];
    q.z = dz * rstd * g[c + 2] + b[c + 2];
    q.w = dw * rstd * g[c + 3] + b[c + 3];
    ((uint2*)(out + (size_t)row * DM))[threadIdx.x] = cvt4(q);
}

// ---------------- fp16 tensor-core GEMM --------------------------------------
// CTA 128x128, 8 warps (2x4), warp 64x32; 5-stage cp.async, distance 3, BK=32.
// epi: 2:Ch=gelu(v+b) 3:Cf+=v 5:Ch=softplus(v+b) 6:Ch=v 7:Cf=(Cf+v+b)*mask(+out2)
#define SROWH 40                           // halves per smem row (80 B)
#define ABUF  (128 * SROWH * 2)            // 10240 B per stage per matrix
#define NSTG  5
#define SMEM10 (2 * NSTG * ABUF)           // 102400 B

__global__ __launch_bounds__(256, 2) void k_gemm_tc(
    const __half* __restrict__ A, const __half* __restrict__ W,
    float* __restrict__ Cf, __half* __restrict__ Ch, const float* __restrict__ bias,
    const int* __restrict__ lenp, float* __restrict__ out2,
    int N, int K, int lda, int ldw, int ldc, int epi) {
    extern __shared__ __half smh[];
    const int tid = threadIdx.x;
    const int lane = tid & 31;
    const int wid = tid >> 5;
    const int wm = wid & 1, wn = wid >> 1;
    const int g = lane >> 2, tig = lane & 3;
    const int bM = blockIdx.y * 128, bN = blockIdx.x * 128;

    const int lrow = tid >> 1;
    const int lc0 = (tid & 1) << 1;
    const __half* Ag = A + (size_t)(bM + lrow) * lda;
    int wr = bN + lrow; if (wr >= N) wr = N - 1;
    const __half* Wg = W + (size_t)wr * ldw;

    const uint32_t sA = (uint32_t)__cvta_generic_to_shared(smh);
    const uint32_t sB = sA + NSTG * ABUF;
    const uint32_t dRow = (uint32_t)lrow * (SROWH * 2);

    const uint32_t aoff = (uint32_t)((wm * 64 + (lane & 15)) * (SROWH * 2) + ((lane >> 4) << 4));
    const uint32_t boff = (uint32_t)((wn * 32 + ((lane >> 4) << 3) + (lane & 7)) * (SROWH * 2)
                                     + (((lane >> 3) & 1) << 4));

    float acc[4][4][4];
    #pragma unroll
    for (int i = 0; i < 4; i++)
        #pragma unroll
        for (int j = 0; j < 4; j++)
            #pragma unroll
            for (int q = 0; q < 4; q++) acc[i][j][q] = 0.f;

    const int KT = K / 32;

    // prologue: stages 0..2 (guarded for short K)
    #pragma unroll
    for (int s = 0; s < 3; s++) {
        if (s < KT) {
            const int k2 = s * 32;
            #pragma unroll
            for (int c = 0; c < 2; c++) {
                cpasync16(sA + s * ABUF + dRow + (lc0 + c) * 16, Ag + k2 + (lc0 + c) * 8);
                cpasync16(sB + s * ABUF + dRow + (lc0 + c) * 16, Wg + k2 + (lc0 + c) * 8);
            }
            asm volatile("cp.async.commit_group;");
        }
    }

    int s_r = 0;       // read stage
    int s_w = 3;       // write stage (j+3)
    for (int j = 0; j < KT; j++) {
        const int rem = KT - 1 - j;
        if (rem >= 3) {
            const int k2 = (j + 3) * 32;
            #pragma unroll
            for (int c = 0; c < 2; c++) {
                cpasync16(sA + s_w * ABUF + dRow + (lc0 + c) * 16, Ag + k2 + (lc0 + c) * 8);
                cpasync16(sB + s_w * ABUF + dRow + (lc0 + c) * 16, Wg + k2 + (lc0 + c) * 8);
            }
            asm volatile("cp.async.commit_group;");
            if (++s_w == NSTG) s_w = 0;
            asm volatile("cp.async.wait_group 3;");
        } else if (rem == 2) {
            asm volatile("cp.async.wait_group 2;");
        } else if (rem == 1) {
            asm volatile("cp.async.wait_group 1;");
        } else {
            asm volatile("cp.async.wait_group 0;");
        }
        __syncthreads();

        const uint32_t ab = sA + s_r * ABUF;
        const uint32_t bb = sB + s_r * ABUF;
        if (++s_r == NSTG) s_r = 0;
        #pragma unroll
        for (int ks = 0; ks < 2; ks++) {
            uint32_t af[4][4], bf[4][2];
            #pragma unroll
            for (int i = 0; i < 4; i++)
                LDSM4(af[i][0], af[i][1], af[i][2], af[i][3],
                      ab + aoff + (uint32_t)(i * 16 * SROWH * 2 + ks * 32));
            #pragma unroll
            for (int jp = 0; jp < 2; jp++)
                LDSM4(bf[2*jp][0], bf[2*jp][1], bf[2*jp+1][0], bf[2*jp+1][1],
                      bb + boff + (uint32_t)(jp * 16 * SROWH * 2 + ks * 32));
            #pragma unroll
            for (int i = 0; i < 4; i++)
                #pragma unroll
                for (int jj = 0; jj < 4; jj++)
                    mma_f16(acc[i][jj], af[i][0], af[i][1], af[i][2], af[i][3],
                            bf[jj][0], bf[jj][1]);
        }
    }

    // epilogue
    #pragma unroll
    for (int i = 0; i < 4; i++) {
        const int r0 = bM + wm * 64 + i * 16 + g;
        #pragma unroll
        for (int j = 0; j < 4; j++) {
            const int cn = bN + wn * 32 + j * 8 + tig * 2;
            #pragma unroll
            for (int q = 0; q < 4; q++) {
                const int r = r0 + (q >> 1) * 8;
                const int c = cn + (q & 1);
                if (c >= N) continue;
                float v = acc[i][j][q];
                if (epi == 2) {
                    float u = v + bias[c];
                    Ch[(size_t)r * ldc + c] =
                        __float2half_rn(0.5f * u * (1.0f + erff(u * 0.70710678118654752f)));
                } else if (epi == 3) { Cf[(size_t)r * ldc + c] += v; }
                else if (epi == 5) {
                    float u = v + bias[c];
                    Ch[(size_t)r * ldc + c] =
                        __float2half_rn((u > 20.f) ? u : log1pf(expf(u)));
                } else if (epi == 6) { Ch[(size_t)r * ldc + c] = __float2half_rn(v); }
                else {
                    int t = r & (TSEQ - 1), bidx = r >> 11;
                    float o = Cf[(size_t)r * ldc + c] + v + bias[c];
                    o = (t < lenp[bidx]) ? o : 0.f;
                    Cf[(size_t)r * ldc + c] = o;
                    if (out2) out2[(size_t)r * ldc + c] = o;
                }
            }
        }
    }
}

// ---------------- causal depthwise conv (k=4) + silu, half2 ------------------
__global__ void k_conv(const __half* __restrict__ xz, const float* __restrict__ cw,
                       const float* __restrict__ cb, __half* __restrict__ xc) {
    int idx = blockIdx.x * 256 + threadIdx.x;    // over MROWS*DI/2
    int d2 = idx & (DI / 2 - 1);
    int m = idx >> 10;
    int t = m & (TSEQ - 1);
    int d = d2 * 2;
    float a0 = cb[d], a1 = cb[d + 1];
    #pragma unroll
    for (int k = 0; k < 4; k++) {
        int tt = t + k - 3;
        if (tt >= 0) {
            __half2 hv = *(const __half2*)(xz + (size_t)(m + k - 3) * (2 * DI) + d);
            a0 += __low2float(hv)  * cw[d * 4 + k];
            a1 += __high2float(hv) * cw[(d + 1) * 4 + k];
        }
    }
    float s0 = a0 / (1.0f + expf(-a0));
    float s1 = a1 / (1.0f + expf(-a1));
    *(__half2*)(xc + (size_t)m * DI + d) = __floats2half2_rn(s0, s1);
}

// ---------------- scan pass A -------------------------------------------------
__global__ __launch_bounds__(256) void k_scanA(
    const __half* __restrict__ dt, const __half* __restrict__ xc,
    const __half* __restrict__ xd, const float* __restrict__ Alog,
    float* __restrict__ gP, float* __restrict__ gS) {
    __shared__ float shB[CL][DS_];
    int b = blockIdx.z, c = blockIdx.y;
    int d = blockIdx.x * 256 + threadIdx.x;
    int mbase = b * TSEQ + c * CL;
    for (int idx = threadIdx.x; idx < CL * DS_; idx += 256) {
        int t = idx >> 4, col = idx & 15;
        shB[t][col] = __half2float(xd[(size_t)(mbase + t) * 96 + 64 + col]);
    }
    __syncthreads();
    float r[DS_];
    bool fast = true;
    #pragma unroll
    for (int n = 0; n < DS_; n++) {
        r[n] = expf(Alog[(size_t)d * DS_ + n]);
        fast = fast && (fabsf(r[n] - (float)(n + 1)) < 1e-3f * (float)(n + 1));
    }
    float P[DS_], S[DS_];
    #pragma unroll
    for (int n = 0; n < DS_; n++) { P[n] = 1.f; S[n] = 0.f; }
    for (int t = 0; t < CL; t++) {
        int m = mbase + t;
        float dv = __half2float(dt[(size_t)m * DI + d]);
        float xv = __half2float(xc[(size_t)m * DI + d]);
        float u = xv * dv;
        float dA[DS_];
        if (fast) {
            float e = expf(-dv);
            float p = 1.f;
            #pragma unroll
            for (int n = 0; n < DS_; n++) { p *= e; dA[n] = p; }
        } else {
            #pragma unroll
            for (int n = 0; n < DS_; n++) dA[n] = expf(-dv * r[n]);
        }
        #pragma unroll
        for (int n = 0; n < DS_; n++) {
            S[n] = S[n] * dA[n] + u * shB[t][n];
            P[n] *= dA[n];
        }
    }
    size_t base = (((size_t)b * NC + c) * DI + d) * DS_;
    #pragma unroll
    for (int n = 0; n < DS_; n += 4) {
        *(float4*)(gP + base + n) = make_float4(P[n], P[n+1], P[n+2], P[n+3]);
        *(float4*)(gS + base + n) = make_float4(S[n], S[n+1], S[n+2], S[n+3]);
    }
}

// ---------------- scan pass B -------------------------------------------------
__global__ void k_scanB(const float* __restrict__ gP, const float* __restrict__ gS,
                        float* __restrict__ gI) {
    int idx = blockIdx.x * 256 + threadIdx.x;
    int b = idx >> 11, d = idx & (DI - 1);
    float s[DS_];
    #pragma unroll
    for (int n = 0; n < DS_; n++) s[n] = 0.f;
    for (int c = 0; c < NC; c++) {
        size_t base = (((size_t)b * NC + c) * DI + d) * DS_;
        #pragma unroll
        for (int n = 0; n < DS_; n += 4)
            *(float4*)(gI + base + n) = make_float4(s[n], s[n+1], s[n+2], s[n+3]);
        #pragma unroll
        for (int n = 0; n < DS_; n += 4) {
            float4 P = *(const float4*)(gP + base + n);
            float4 S = *(const float4*)(gS + base + n);
            s[n+0] = s[n+0] * P.x + S.x;
            s[n+1] = s[n+1] * P.y + S.y;
            s[n+2] = s[n+2] * P.z + S.z;
            s[n+3] = s[n+3] * P.w + S.w;
        }
    }
}

// ---------------- scan pass C -------------------------------------------------
__global__ __launch_bounds__(256) void k_scanC(
    const __half* __restrict__ dt, const __half* __restrict__ xc,
    const __half* __restrict__ xd, const __half* __restrict__ xz,
    const float* __restrict__ Alog, const float* __restrict__ Dsk,
    const float* __restrict__ gI, __half* __restrict__ ym) {
    __shared__ float shB[CL][DS_];
    __shared__ float shC[CL][DS_];
    int b = blockIdx.z, c = blockIdx.y;
    int d = blockIdx.x * 256 + threadIdx.x;
    int mbase = b * TSEQ + c * CL;
    for (int idx = threadIdx.x; idx < CL * 32; idx += 256) {
        int t = idx >> 5, col = idx & 31;
        float v = __half2float(xd[(size_t)(mbase + t) * 96 + 64 + col]);
        if (col < 16) shB[t][col] = v;
        else shC[t][col - 16] = v;
    }
    __syncthreads();
    float r[DS_];
    bool fast = true;
    #pragma unroll
    for (int n = 0; n < DS_; n++) {
        r[n] = expf(Alog[(size_t)d * DS_ + n]);
        fast = fast && (fabsf(r[n] - (float)(n + 1)) < 1e-3f * (float)(n + 1));
    }
    float dskip = Dsk[d];
    float s[DS_];
    size_t base = (((size_t)b * NC + c) * DI + d) * DS_;
    #pragma unroll
    for (int n = 0; n < DS_; n += 4) {
        float4 v = *(const float4*)(gI + base + n);
        s[n+0] = v.x; s[n+1] = v.y; s[n+2] = v.z; s[n+3] = v.w;
    }
    for (int t = 0; t < CL; t++) {
        int m = mbase + t;
        float dv = __half2float(dt[(size_t)m * DI + d]);
        float xv = __half2float(xc[(size_t)m * DI + d]);
        float u = xv * dv;
        float dA[DS_];
        if (fast) {
            float e = expf(-dv);
            float p = 1.f;
            #pragma unroll
            for (int n = 0; n < DS_; n++) { p *= e; dA[n] = p; }
        } else {
            #pragma unroll
            for (int n = 0; n < DS_; n++) dA[n] = expf(-dv * r[n]);
        }
        float y = 0.f;
        #pragma unroll
        for (int n = 0; n < DS_; n++) {
            s[n] = s[n] * dA[n] + u * shB[t][n];
            y += s[n] * shC[t][n];
        }
        float z = __half2float(xz[(size_t)m * (2 * DI) + DI + d]);
        float sg = 1.0f / (1.0f + expf(-z));
        ym[(size_t)m * DI + d] = __float2half_rn((y + dskip * xv) * (z * sg));
    }
}

// ---------------- host orchestration -------------------------------------------
static void launch_gemm(const __half* A, const __half* W,
                        float* Cf, __half* Ch, const float* bias,
                        const int* lenp, float* out2,
                        int N, int K, int lda, int ldc, int epi) {
    dim3 grid((N + 127) / 128, MROWS / 128);
    k_gemm_tc<<<grid, 256, SMEM10>>>(A, W, Cf, Ch, bias, lenp, out2, N, K, lda, K, ldc, epi);
}

extern "C" void kernel_launch(void* const* d_in, const int* in_sizes, int n_in,
                              void* d_out, int out_size) {
    const float* x       = (const float*)d_in[0];
    const int*   lengths = (const int*)  d_in[1];
    const float* ln0_g   = (const float*)d_in[2];
    const float* ln0_b   = (const float*)d_in[3];
    const float* ln1_g   = (const float*)d_in[4];
    const float* ln1_b   = (const float*)d_in[5];
    const float* in_w    = (const float*)d_in[6];
    const float* conv_w  = (const float*)d_in[7];
    const float* conv_b  = (const float*)d_in[8];
    const float* xp_w    = (const float*)d_in[9];
    const float* dt_w    = (const float*)d_in[10];
    const float* dt_b    = (const float*)d_in[11];
    const float* A_log   = (const float*)d_in[12];
    const float* D_skip  = (const float*)d_in[13];
    const float* out_w   = (const float*)d_in[14];
    const float* ln2_g   = (const float*)d_in[15];
    const float* ln2_b   = (const float*)d_in[16];
    const float* f1_w    = (const float*)d_in[17];
    const float* f1_b    = (const float*)d_in[18];
    const float* f2_w    = (const float*)d_in[19];
    const float* f2_b    = (const float*)d_in[20];

    cudaFuncSetAttribute(k_gemm_tc, cudaFuncAttributeMaxDynamicSharedMemorySize, SMEM10);

    float *pX, *pP, *pS, *pI;
    __half *pXn, *pXz, *pXc, *pXd, *pDt, *pY, *pF, *pWa;
    cudaGetSymbolAddress((void**)&pX,  g_X);
    cudaGetSymbolAddress((void**)&pXn, g_Xn);
    cudaGetSymbolAddress((void**)&pXz, g_xz);
    cudaGetSymbolAddress((void**)&pXc, g_xc);
    cudaGetSymbolAddress((void**)&pXd, g_xd);
    cudaGetSymbolAddress((void**)&pDt, g_dt);
    cudaGetSymbolAddress((void**)&pY,  g_ym);
    cudaGetSymbolAddress((void**)&pF,  g_ffn);
    cudaGetSymbolAddress((void**)&pP,  g_cP);
    cudaGetSymbolAddress((void**)&pS,  g_cS);
    cudaGetSymbolAddress((void**)&pI,  g_cI);
    cudaGetSymbolAddress((void**)&pWa, g_wa);

    // [1] in_proj weights
    k_round<<<(SZ_IN / 4 + 255) / 256, 256>>>(in_w, pWa + OW_IN, SZ_IN / 4);
    // [2] remaining weights, one packed launch
    {
        int na = SZ_XP / 4, nb = SZ_DT / 4, nc2 = SZ_OUT / 4, nd = SZ_F1 / 4, ne = SZ_F2 / 4;
        int tot = na + nb + nc2 + nd + ne;
        k_round5<<<(tot + 255) / 256, 256>>>(
            xp_w,  pWa + OW_XP,  na,
            dt_w,  pWa + OW_DT,  nb,
            out_w, pWa + OW_OUT, nc2,
            f1_w,  pWa + OW_F1,  nd,
            f2_w,  pWa + OW_F2,  ne);
    }
    // [3] fused PE + ln0 + ln1(layer0) -> X, Xn
    k_peln2<<<MROWS, 256>>>(x, pX, pXn, ln0_g, ln0_b, ln1_g, ln1_b);

    for (int i = 0; i < 4; i++) {
        // --- Mamba block ---
        if (i > 0)
            k_ln_h<<<MROWS, 256>>>(pX, pXn, ln1_g + i * DM, ln1_b + i * DM);
        // [4] first in_proj GEMM -> ncu capture slot
        launch_gemm(pXn, pWa + OW_IN + (size_t)i * 2 * DI * DM, nullptr, pXz, nullptr,
                    nullptr, nullptr, 2 * DI, DM, DM, 2 * DI, 6);
        k_conv<<<(MROWS * DI / 2) / 256, 256>>>(pXz, conv_w + (size_t)i * DI * 4,
                                                conv_b + (size_t)i * DI, pXc);
        launch_gemm(pXc, pWa + OW_XP + (size_t)i * 96 * DI, nullptr, pXd, nullptr,
                    nullptr, nullptr, 96, DI, DI, 96, 6);
        launch_gemm(pXd, pWa + OW_DT + (size_t)i * DI * DTR, nullptr, pDt,
                    dt_b + (size_t)i * DI, nullptr, nullptr, DI, DTR, 96, DI, 5);
        dim3 sg(DI / 256, NC, BB);
        k_scanA<<<sg, 256>>>(pDt, pXc, pXd, A_log + (size_t)i * DI * DS_, pP, pS);
        k_scanB<<<(BB * DI) / 256, 256>>>(pP, pS, pI);
        k_scanC<<<sg, 256>>>(pDt, pXc, pXd, pXz, A_log + (size_t)i * DI * DS_,
                             D_skip + (size_t)i * DI, pI, pY);
        launch_gemm(pY, pWa + OW_OUT + (size_t)i * DM * DI, pX, nullptr, nullptr,
                    nullptr, nullptr, DM, DI, DI, DM, 3);
        // --- FFN block ---
        k_ln_h<<<MROWS, 256>>>(pX, pXn, ln2_g + i * DM, ln2_b + i * DM);
        launch_gemm(pXn, pWa + OW_F1 + (size_t)i * FFND * DM, nullptr, pF,
                    f1_b + (size_t)i * FFND, nullptr, nullptr, FFND, DM, DM, FFND, 2);
        launch_gemm(pF, pWa + OW_F2 + (size_t)i * DM * FFND, pX, nullptr,
                    f2_b + (size_t)i * DM, lengths,
                    (i == 3) ? (float*)d_out : nullptr, DM, FFND, FFND, DM, 7);
    }
}